// round 2
// baseline (speedup 1.0000x reference)
#include <cuda_runtime.h>
#include <cuda_bf16.h>
#include <math.h>

// Problem constants
#define BB 32
#define TT 256
#define DD 1024
#define HH 8
#define DH 128
#define HID 256
#define MTOT (BB*TT)          // 8192
#define XF 2560

// ------------------------- scratch (static device memory) -------------------
__device__ float g_h [MTOT*DD];
__device__ float g_q [MTOT*DD];
__device__ float g_k [MTOT*DD];
__device__ float g_v [MTOT*DD];
__device__ float g_ao[MTOT*DD];
__device__ float g_gxf[MTOT*768];
__device__ float g_gxb[MTOT*768];
__device__ float g_hstate[2*2*BB*HID];   // [dir][buf][batch][unit]
__device__ unsigned g_bar[16];
__device__ int g_len[BB];

// ------------------------- prep: lengths + barrier reset --------------------
__global__ void prep_kernel(const int* __restrict__ mask) {
    int b = blockIdx.x;
    __shared__ int red[256];
    red[threadIdx.x] = mask[b*TT + threadIdx.x];
    __syncthreads();
    for (int st = 128; st > 0; st >>= 1) {
        if (threadIdx.x < st) red[threadIdx.x] += red[threadIdx.x + st];
        __syncthreads();
    }
    if (threadIdx.x == 0) g_len[b] = red[0];
    if (b == 0 && threadIdx.x < 16) g_bar[threadIdx.x] = 0u;
}

// ------------------------- SGEMM: C = A*B (+bias) (+res) --------------------
// A: [M,K] row-major with lda.
// BT=false: B is [K,N] row-major.  BT=true: B is [N,K] row-major (B^T used).
// RESID: C = res + A*B + bias, res has leading dim ldr.
// Requires M%128==0, N%128==0, K%8==0.
template<bool BT, bool RESID>
__global__ __launch_bounds__(256) void sgemm(
    const float* __restrict__ A, int lda,
    const float* __restrict__ B,
    const float* __restrict__ bias,
    const float* __restrict__ R, int ldr,
    float* __restrict__ C,
    int M, int N, int K)
{
    __shared__ __align__(16) float As[8][128];
    __shared__ __align__(16) float Bs[8][128];

    int tid = threadIdx.x;
    int bm = blockIdx.y * 128;
    int bn = blockIdx.x * 128;
    int tr = tid / 16;         // 0..15
    int tc = tid % 16;         // 0..15

    float acc[8][8];
#pragma unroll
    for (int i = 0; i < 8; i++)
#pragma unroll
        for (int j = 0; j < 8; j++) acc[i][j] = 0.f;

    for (int k0 = 0; k0 < K; k0 += 8) {
        // load A tile (128 x 8), store transposed As[k][m]
        {
            int m  = tid >> 1;
            int kq = (tid & 1) * 4;
            float4 av = *(const float4*)(A + (size_t)(bm + m) * lda + k0 + kq);
            As[kq+0][m] = av.x; As[kq+1][m] = av.y;
            As[kq+2][m] = av.z; As[kq+3][m] = av.w;
        }
        if (!BT) {
            int kk = tid >> 5;
            int n  = (tid & 31) * 4;
            *(float4*)&Bs[kk][n] = *(const float4*)(B + (size_t)(k0 + kk) * N + bn + n);
        } else {
            int n  = tid >> 1;
            int kq = (tid & 1) * 4;
            float4 bv = *(const float4*)(B + (size_t)(bn + n) * K + k0 + kq);
            Bs[kq+0][n] = bv.x; Bs[kq+1][n] = bv.y;
            Bs[kq+2][n] = bv.z; Bs[kq+3][n] = bv.w;
        }
        __syncthreads();

#pragma unroll
        for (int kk = 0; kk < 8; kk++) {
            float a[8], bb[8];
            *(float4*)&a[0]  = *(const float4*)&As[kk][tr*8];
            *(float4*)&a[4]  = *(const float4*)&As[kk][tr*8 + 4];
            *(float4*)&bb[0] = *(const float4*)&Bs[kk][tc*8];
            *(float4*)&bb[4] = *(const float4*)&Bs[kk][tc*8 + 4];
#pragma unroll
            for (int i = 0; i < 8; i++)
#pragma unroll
                for (int j = 0; j < 8; j++)
                    acc[i][j] += a[i] * bb[j];
        }
        __syncthreads();
    }

    // epilogue
#pragma unroll
    for (int i = 0; i < 8; i++) {
        int m = bm + tr*8 + i;
#pragma unroll
        for (int j = 0; j < 8; j += 4) {
            int n = bn + tc*8 + j;
            float4 r;
            r.x = acc[i][j+0] + bias[n+0];
            r.y = acc[i][j+1] + bias[n+1];
            r.z = acc[i][j+2] + bias[n+2];
            r.w = acc[i][j+3] + bias[n+3];
            if (RESID) {
                float4 rr = *(const float4*)(R + (size_t)m * ldr + n);
                r.x += rr.x; r.y += rr.y; r.z += rr.z; r.w += rr.w;
            }
            *(float4*)(C + (size_t)m * N + n) = r;
        }
    }
}

// ------------------------- banded attention ---------------------------------
// grid (T, B), block 256 = 8 warps (one warp per head per query t)
__global__ __launch_bounds__(256) void band_attn(
    const float* __restrict__ q, const float* __restrict__ k,
    const float* __restrict__ v, float* __restrict__ o)
{
    int t = blockIdx.x, b = blockIdx.y;
    int hh = threadIdx.x >> 5;
    int lane = threadIdx.x & 31;
    const float scale = 0.088388347648318447f;  // 1/sqrt(128)

    size_t base = ((size_t)(b*TT + t))*DD + hh*DH + lane*4;
    float4 qv = *(const float4*)(q + base);

    float s[7];
    float m = -1e30f;
#pragma unroll
    for (int jj = 0; jj < 7; jj++) {
        int j = t - 3 + jj;
        bool ok = (j >= 0) && (j < TT);
        int jc = j < 0 ? 0 : (j > TT-1 ? TT-1 : j);
        size_t kb = ((size_t)(b*TT + jc))*DD + hh*DH + lane*4;
        float4 kv = *(const float4*)(k + kb);
        float d = qv.x*kv.x + qv.y*kv.y + qv.z*kv.z + qv.w*kv.w;
        d += __shfl_xor_sync(0xffffffffu, d, 16);
        d += __shfl_xor_sync(0xffffffffu, d, 8);
        d += __shfl_xor_sync(0xffffffffu, d, 4);
        d += __shfl_xor_sync(0xffffffffu, d, 2);
        d += __shfl_xor_sync(0xffffffffu, d, 1);
        d *= scale;
        s[jj] = ok ? d : -1e30f;
        m = fmaxf(m, s[jj]);
    }
    float sum = 0.f;
#pragma unroll
    for (int jj = 0; jj < 7; jj++) { s[jj] = expf(s[jj] - m); sum += s[jj]; }
    float inv = 1.f / sum;

    float4 acc = make_float4(0.f, 0.f, 0.f, 0.f);
#pragma unroll
    for (int jj = 0; jj < 7; jj++) {
        int j = t - 3 + jj;
        int jc = j < 0 ? 0 : (j > TT-1 ? TT-1 : j);
        size_t vb = ((size_t)(b*TT + jc))*DD + hh*DH + lane*4;
        float4 vv = *(const float4*)(v + vb);
        float p = s[jj] * inv;
        acc.x += p*vv.x; acc.y += p*vv.y; acc.z += p*vv.z; acc.w += p*vv.w;
    }
    *(float4*)(o + base) = acc;
}

// ------------------------- persistent bidirectional GRU ---------------------
// 128 CTAs: dir(2) x unit-group(8, 32 units) x batch-group(8, 4 batches)
// 128 threads: thread = (u 0..31, bl 0..3)
// Barrier: monotonic atomic counter per (dir,batch-group), 8 arrivals/step.
__global__ __launch_bounds__(128) void gru_kernel(
    const float* __restrict__ gxf, const float* __restrict__ gxb,
    const float* __restrict__ Whf, const float* __restrict__ Whb,
    const float* __restrict__ bhf, const float* __restrict__ bhb,
    float* __restrict__ out)
{
    extern __shared__ float sm[];
    float* ws = sm;                   // [3*32][260]
    float* hs = sm + 3*32*260;        // [4][264]

    int cta = blockIdx.x;
    int dir = cta >> 6;
    int ug  = (cta >> 3) & 7;
    int bg  = cta & 7;
    int grp = (dir << 3) | bg;
    int tid = threadIdx.x;
    int u   = tid >> 2;
    int bl  = tid & 3;
    int unit  = ug*32 + u;
    int batch = bg*4 + bl;

    const float* Wh = dir ? Whb : Whf;
    const float* bh = dir ? bhb : bhf;
    const float* gx = dir ? gxb : gxf;

    // one-time weight load: rows {g*256 + ug*32 + uu}, k 0..255
    for (int idx = tid; idx < 3*32*256; idx += 128) {
        int g   = idx >> 13;
        int rem = idx & 8191;
        int uu  = rem >> 8;
        int kk  = rem & 255;
        ws[(g*32 + uu)*260 + kk] = Wh[((g << 8) + ug*32 + uu)*256 + kk];
    }
    float br  = bh[unit];
    float bz  = bh[256 + unit];
    float bnn = bh[512 + unit];
    int len = g_len[batch];

    // init h buffer 0 (each thread owns one (batch,unit) element)
    __stcg(&g_hstate[((dir*2 + 0)*BB + batch)*HID + unit], 0.f);
    __threadfence();
    __syncthreads();
    if (tid == 0) atomicAdd(&g_bar[grp], 1u);

    const float* wr = &ws[(0*32 + u)*260];
    const float* wz = &ws[(1*32 + u)*260];
    const float* wn = &ws[(2*32 + u)*260];

    unsigned target = 8u;
    for (int s = 0; s < TT; s++, target += 8u) {
        if (tid == 0) { while (atomicAdd(&g_bar[grp], 0u) < target) {} }
        __syncthreads();
        __threadfence();

        // stage full h (4 batches x 256) from global (L2, bypass L1)
        {
            const float* src = &g_hstate[((dir*2 + (s & 1))*BB + bg*4)*HID];
#pragma unroll
            for (int i = 0; i < 8; i++) {
                int idx = tid + i*128;
                int b2 = idx >> 8, k2 = idx & 255;
                hs[b2*264 + k2] = __ldcg(src + b2*256 + k2);
            }
        }
        __syncthreads();

        float4 ar = make_float4(0,0,0,0), az = ar, an = ar;
        const float* hb = &hs[bl*264];
#pragma unroll 8
        for (int kk = 0; kk < 256; kk += 4) {
            float4 h4 = *(const float4*)(hb + kk);
            float4 w1 = *(const float4*)(wr + kk);
            float4 w2 = *(const float4*)(wz + kk);
            float4 w3 = *(const float4*)(wn + kk);
            ar.x += h4.x*w1.x; ar.y += h4.y*w1.y; ar.z += h4.z*w1.z; ar.w += h4.w*w1.w;
            az.x += h4.x*w2.x; az.y += h4.y*w2.y; az.z += h4.z*w2.z; az.w += h4.w*w2.w;
            an.x += h4.x*w3.x; an.y += h4.y*w3.y; an.z += h4.z*w3.z; an.w += h4.w*w3.w;
        }
        float ghr = ar.x + ar.y + ar.z + ar.w;
        float ghz = az.x + az.y + az.z + az.w;
        float ghn = an.x + an.y + an.z + an.w;

        int tt;
        if (dir == 0) tt = s;
        else { int ti = len - 1 - s; tt = ti < 0 ? 0 : ti; }

        const float* gxp = gx + ((size_t)batch*TT + tt)*768;
        float gr = gxp[unit];
        float gz = gxp[256 + unit];
        float gn = gxp[512 + unit];

        float r = 1.f / (1.f + expf(-(gr + ghr + br)));
        float z = 1.f / (1.f + expf(-(gz + ghz + bz)));
        float n = tanhf(gn + r*(ghn + bnn));
        float hp = hs[bl*264 + unit];
        float hn = (1.f - z)*n + z*hp;

        __stcg(&g_hstate[((dir*2 + ((s+1) & 1))*BB + batch)*HID + unit], hn);

        if (s < len) {
            int tout = (dir == 0) ? s : (len - 1 - s);
            float* op = out + ((size_t)batch*TT + tout)*512 + dir*256 + unit;
            *op += hn;   // out holds x_face; each element written exactly once
        }
        __syncthreads();
        __threadfence();
        if (tid == 0) atomicAdd(&g_bar[grp], 1u);
    }
}

// ------------------------- launch ------------------------------------------
extern "C" void kernel_launch(void* const* d_in, const int* in_sizes, int n_in,
                              void* d_out, int out_size)
{
    const float* x      = (const float*)d_in[0];
    const int*   mask   = (const int*)  d_in[1];
    const float* W_tran = (const float*)d_in[2];
    const float* b_tran = (const float*)d_in[3];
    const float* Wq     = (const float*)d_in[4];
    const float* bq     = (const float*)d_in[5];
    const float* Wk     = (const float*)d_in[6];
    const float* bk     = (const float*)d_in[7];
    const float* Wv     = (const float*)d_in[8];
    const float* bv     = (const float*)d_in[9];
    const float* Wo     = (const float*)d_in[10];
    const float* bo     = (const float*)d_in[11];
    const float* Wihf   = (const float*)d_in[12];
    const float* Whhf   = (const float*)d_in[13];
    const float* bihf   = (const float*)d_in[14];
    const float* bhhf   = (const float*)d_in[15];
    const float* Wihb   = (const float*)d_in[16];
    const float* Whhb   = (const float*)d_in[17];
    const float* bihb   = (const float*)d_in[18];
    const float* bhhb   = (const float*)d_in[19];
    float* out = (float*)d_out;

    float *hbuf, *qb, *kb, *vb, *aob, *gxfb, *gxbb;
    cudaGetSymbolAddress((void**)&hbuf,  g_h);
    cudaGetSymbolAddress((void**)&qb,    g_q);
    cudaGetSymbolAddress((void**)&kb,    g_k);
    cudaGetSymbolAddress((void**)&vb,    g_v);
    cudaGetSymbolAddress((void**)&aob,   g_ao);
    cudaGetSymbolAddress((void**)&gxfb,  g_gxf);
    cudaGetSymbolAddress((void**)&gxbb,  g_gxb);

    const int smem_gru = (3*32*260 + 4*264) * 4;  // 104,064 B
    cudaFuncSetAttribute(gru_kernel, cudaFuncAttributeMaxDynamicSharedMemorySize, 112*1024);

    dim3 blk(256);

    prep_kernel<<<BB, 256>>>(mask);

    // x_face -> out
    sgemm<false,false><<<dim3(512/128, MTOT/128), blk>>>(
        x + 1024, XF, W_tran, b_tran, nullptr, 0, out, MTOT, 512, 1536);

    for (int l = 0; l < 2; l++) {
        const float* Ain = (l == 0) ? x : hbuf;
        int lda = (l == 0) ? XF : DD;
        size_t wo = (size_t)l * DD * DD;
        size_t bo_ = (size_t)l * DD;

        sgemm<false,false><<<dim3(8, 64), blk>>>(Ain, lda, Wq + wo, bq + bo_, nullptr, 0, qb, MTOT, DD, DD);
        sgemm<false,false><<<dim3(8, 64), blk>>>(Ain, lda, Wk + wo, bk + bo_, nullptr, 0, kb, MTOT, DD, DD);
        sgemm<false,false><<<dim3(8, 64), blk>>>(Ain, lda, Wv + wo, bv + bo_, nullptr, 0, vb, MTOT, DD, DD);

        band_attn<<<dim3(TT, BB), 256>>>(qb, kb, vb, aob);

        sgemm<false,true><<<dim3(8, 64), blk>>>(aob, DD, Wo + wo, bo + bo_, Ain, lda, hbuf, MTOT, DD, DD);
    }

    // GRU input projections (B transposed: W_ih is [768,1024])
    sgemm<true,false><<<dim3(6, 64), blk>>>(hbuf, DD, Wihf, bihf, nullptr, 0, gxfb, MTOT, 768, DD);
    sgemm<true,false><<<dim3(6, 64), blk>>>(hbuf, DD, Wihb, bihb, nullptr, 0, gxbb, MTOT, 768, DD);

    // persistent bidirectional GRU, writes out += ys
    gru_kernel<<<128, 128, smem_gru>>>(gxfb, gxbb, Whhf, Whhb, bhhf, bhhb, out);
}

// round 4
// speedup vs baseline: 1.8784x; 1.8784x over previous
#include <cuda_runtime.h>
#include <cuda_bf16.h>
#include <math.h>
#include <stdint.h>

// Problem constants
#define BB 32
#define TT 256
#define DD 1024
#define HH 8
#define DH 128
#define HID 256
#define MTOT (BB*TT)          // 8192
#define XF 2560

// ------------------------- scratch (static device memory) -------------------
__device__ float g_h [MTOT*DD];
__device__ float g_q [MTOT*DD];
__device__ float g_k [MTOT*DD];
__device__ float g_v [MTOT*DD];
__device__ float g_ao[MTOT*DD];
__device__ float g_gxf[MTOT*768];
__device__ float g_gxb[MTOT*768];
__device__ float g_hstate[2*2*BB*HID];   // [dir][buf][batch][unit]
__device__ unsigned g_bar[16];
__device__ int g_len[BB];

// split bf16 weights, [N][K] layout
#define OFF_TRAN 0
#define OFF_QKVO 786432
#define OFF_IHF  9175040
#define OFF_IHB  9961472
#define WSPLIT_ELEMS 10747904
__device__ __nv_bfloat16 g_Whi[WSPLIT_ELEMS];
__device__ __nv_bfloat16 g_Wlo[WSPLIT_ELEMS];

// ------------------------- helpers ------------------------------------------
__device__ __forceinline__ uint32_t smem_u32(const void* p) {
    uint32_t a;
    asm("{ .reg .u64 t; cvta.to.shared.u64 t, %1; cvt.u32.u64 %0, t; }" : "=r"(a) : "l"(p));
    return a;
}
__device__ __forceinline__ void ldsm4(uint32_t* r, uint32_t addr) {
    asm volatile("ldmatrix.sync.aligned.m8n8.x4.shared.b16 {%0,%1,%2,%3}, [%4];"
        : "=r"(r[0]), "=r"(r[1]), "=r"(r[2]), "=r"(r[3]) : "r"(addr));
}
__device__ __forceinline__ void mma_bf16(float* c, const uint32_t* a, uint32_t b0, uint32_t b1) {
    asm volatile(
        "mma.sync.aligned.m16n8k16.row.col.f32.bf16.bf16.f32 "
        "{%0,%1,%2,%3}, {%4,%5,%6,%7}, {%8,%9}, {%0,%1,%2,%3};"
        : "+f"(c[0]), "+f"(c[1]), "+f"(c[2]), "+f"(c[3])
        : "r"(a[0]), "r"(a[1]), "r"(a[2]), "r"(a[3]), "r"(b0), "r"(b1));
}

// ------------------------- prep: lengths + barrier reset --------------------
__global__ void prep_kernel(const int* __restrict__ mask) {
    int b = blockIdx.x;
    __shared__ int red[256];
    red[threadIdx.x] = mask[b*TT + threadIdx.x];
    __syncthreads();
    for (int st = 128; st > 0; st >>= 1) {
        if (threadIdx.x < st) red[threadIdx.x] += red[threadIdx.x + st];
        __syncthreads();
    }
    if (threadIdx.x == 0) g_len[b] = red[0];
    if (b == 0 && threadIdx.x < 16) g_bar[threadIdx.x] = 0u;
}

// ------------------------- weight transpose + bf16 split --------------------
// W: [K][N] row-major -> out hi/lo: [N][K]
__global__ __launch_bounds__(256) void wsplit_t(
    const float* __restrict__ W, __nv_bfloat16* __restrict__ hi,
    __nv_bfloat16* __restrict__ lo, int K, int N)
{
    __shared__ float ts[32][33];
    int tx = threadIdx.x, ty = threadIdx.y;
    int n0 = blockIdx.x * 32, k0 = blockIdx.y * 32;
#pragma unroll
    for (int i = 0; i < 4; i++)
        ts[ty + i*8][tx] = W[(size_t)(k0 + ty + i*8) * N + n0 + tx];
    __syncthreads();
#pragma unroll
    for (int i = 0; i < 4; i++) {
        int n = n0 + ty + i*8, k = k0 + tx;
        float f = ts[tx][ty + i*8];
        __nv_bfloat16 h = __float2bfloat16_rn(f);
        __nv_bfloat16 l = __float2bfloat16_rn(f - __bfloat162float(h));
        hi[(size_t)n * K + k] = h;
        lo[(size_t)n * K + k] = l;
    }
}

// W already [N][K]: straight split
__global__ __launch_bounds__(256) void wsplit_c(
    const float* __restrict__ W, __nv_bfloat16* __restrict__ hi,
    __nv_bfloat16* __restrict__ lo, int total)
{
    int idx = blockIdx.x * 256 + threadIdx.x;
    if (idx < total) {
        float f = W[idx];
        __nv_bfloat16 h = __float2bfloat16_rn(f);
        __nv_bfloat16 l = __float2bfloat16_rn(f - __bfloat162float(h));
        hi[idx] = h;
        lo[idx] = l;
    }
}

// ------------------------- HMMA bf16x3 GEMM ---------------------------------
// C[M,N] = A[M,K](fp32) * B[N,K](bf16 hi/lo)^T + bias (+R)
// grid (N/128, M/128), 256 threads (8 warps: 4m x 2n), K % 32 == 0.
// SMEM: 2 stages x { A_hi, A_lo: [128][40] bf16; B_hi, B_lo: [128][40] bf16 }
#define TILE_PITCH 40           // bf16 elems per smem row (80 bytes)
#define TILE_BYTES (128*TILE_PITCH*2)   // 10240
#define STAGE_BYTES (4*TILE_BYTES)      // 40960
#define SM_A_HI 0
#define SM_A_LO TILE_BYTES
#define SM_B_HI (2*TILE_BYTES)
#define SM_B_LO (3*TILE_BYTES)
#define GEMM_SMEM (2*STAGE_BYTES)       // 81920

template<bool RESID>
__global__ __launch_bounds__(256) void gemm_tc(
    const float* __restrict__ A, int lda,
    const __nv_bfloat16* __restrict__ Bhi, const __nv_bfloat16* __restrict__ Blo,
    const float* __restrict__ bias,
    const float* __restrict__ R, int ldr,
    float* __restrict__ C, int N, int K)
{
    extern __shared__ char smem[];
    uint32_t sb = smem_u32(smem);
    int tid = threadIdx.x;
    int lane = tid & 31;
    int wid = tid >> 5;
    int warp_m = wid & 3;      // 0..3
    int warp_n = wid >> 2;     // 0..1
    int bn = blockIdx.x * 128, bm = blockIdx.y * 128;

    float acc[2][8][4];
#pragma unroll
    for (int a = 0; a < 2; a++)
#pragma unroll
        for (int b = 0; b < 8; b++)
#pragma unroll
            for (int c = 0; c < 4; c++) acc[a][b][c] = 0.f;

    float4 aReg[4];
    uint4  bhReg[2], blReg[2];

    // ---- LDG helpers (inlined manually) ----
#define LDG_CHUNK(k0)                                                          \
    {                                                                          \
        _Pragma("unroll")                                                      \
        for (int i = 0; i < 4; i++) {                                          \
            int linear = tid + i * 256;                                        \
            int row = linear >> 3, c4 = (linear & 7) * 4;                      \
            aReg[i] = *(const float4*)(A + (size_t)(bm + row) * lda + (k0) + c4);\
        }                                                                      \
        _Pragma("unroll")                                                      \
        for (int i = 0; i < 2; i++) {                                          \
            int linear = tid + i * 256;                                        \
            int row = linear >> 2, c8 = (linear & 3) * 8;                      \
            size_t g = (size_t)(bn + row) * K + (k0) + c8;                     \
            bhReg[i] = *(const uint4*)(Bhi + g);                               \
            blReg[i] = *(const uint4*)(Blo + g);                               \
        }                                                                      \
    }

#define STS_CHUNK(buf)                                                         \
    {                                                                          \
        char* base = smem + (buf) * STAGE_BYTES;                               \
        _Pragma("unroll")                                                      \
        for (int i = 0; i < 4; i++) {                                          \
            int linear = tid + i * 256;                                        \
            int row = linear >> 3, c4 = (linear & 7) * 4;                      \
            float4 f = aReg[i];                                                \
            __nv_bfloat162 h01 = __floats2bfloat162_rn(f.x, f.y);              \
            __nv_bfloat162 h23 = __floats2bfloat162_rn(f.z, f.w);              \
            __nv_bfloat162 l01 = __floats2bfloat162_rn(                        \
                f.x - __bfloat162float(h01.x), f.y - __bfloat162float(h01.y)); \
            __nv_bfloat162 l23 = __floats2bfloat162_rn(                        \
                f.z - __bfloat162float(h23.x), f.w - __bfloat162float(h23.y)); \
            uint32_t off = row * 80 + c4 * 2;                                  \
            uint2 uh, ul;                                                      \
            uh.x = *reinterpret_cast<uint32_t*>(&h01);                         \
            uh.y = *reinterpret_cast<uint32_t*>(&h23);                         \
            ul.x = *reinterpret_cast<uint32_t*>(&l01);                         \
            ul.y = *reinterpret_cast<uint32_t*>(&l23);                         \
            *(uint2*)(base + SM_A_HI + off) = uh;                              \
            *(uint2*)(base + SM_A_LO + off) = ul;                              \
        }                                                                      \
        _Pragma("unroll")                                                      \
        for (int i = 0; i < 2; i++) {                                          \
            int linear = tid + i * 256;                                        \
            int row = linear >> 2, c8 = (linear & 3) * 8;                      \
            uint32_t off = row * 80 + c8 * 2;                                  \
            *(uint4*)(base + SM_B_HI + off) = bhReg[i];                        \
            *(uint4*)(base + SM_B_LO + off) = blReg[i];                        \
        }                                                                      \
    }

    const int NC = K / 32;
    LDG_CHUNK(0);
    STS_CHUNK(0);
    __syncthreads();

    for (int ch = 0; ch < NC; ch++) {
        int nxt = ch + 1;
        if (nxt < NC) LDG_CHUNK(nxt * 32);

        // ---- compute chunk ch from stage (ch&1) ----
        uint32_t sbase = sb + (ch & 1) * STAGE_BYTES;
#pragma unroll
        for (int ks = 0; ks < 2; ks++) {
            int kofs = ks * 32;   // bytes (16 bf16)
            uint32_t ah[2][4], al[2][4];
#pragma unroll
            for (int mf = 0; mf < 2; mf++) {
                uint32_t row = warp_m * 32 + mf * 16 + (lane & 15);
                uint32_t addr = sbase + SM_A_HI + row * 80 + kofs + ((lane >> 4) * 16);
                ldsm4(ah[mf], addr);
                ldsm4(al[mf], addr + TILE_BYTES);   // A_lo
            }
#pragma unroll
            for (int np = 0; np < 4; np++) {
                uint32_t rown = warp_n * 64 + np * 16 + (lane & 7) + ((lane >> 4) << 3);
                uint32_t addr = sbase + SM_B_HI + rown * 80 + kofs + (((lane >> 3) & 1) * 16);
                uint32_t bh[4], bl[4];
                ldsm4(bh, addr);
                ldsm4(bl, addr + TILE_BYTES);       // B_lo
#pragma unroll
                for (int mf = 0; mf < 2; mf++) {
                    mma_bf16(acc[mf][np*2],   ah[mf], bh[0], bh[1]);
                    mma_bf16(acc[mf][np*2],   ah[mf], bl[0], bl[1]);
                    mma_bf16(acc[mf][np*2],   al[mf], bh[0], bh[1]);
                    mma_bf16(acc[mf][np*2+1], ah[mf], bh[2], bh[3]);
                    mma_bf16(acc[mf][np*2+1], ah[mf], bl[2], bl[3]);
                    mma_bf16(acc[mf][np*2+1], al[mf], bh[2], bh[3]);
                }
            }
        }

        if (nxt < NC) STS_CHUNK(nxt & 1);
        __syncthreads();
    }

    // ---- epilogue ----
#pragma unroll
    for (int mf = 0; mf < 2; mf++) {
        int row0 = bm + warp_m * 32 + mf * 16 + (lane >> 2);
        int row1 = row0 + 8;
#pragma unroll
        for (int nf = 0; nf < 8; nf++) {
            int col = bn + warp_n * 64 + nf * 8 + (lane & 3) * 2;
            float2 bs = *(const float2*)(bias + col);
            float* a4 = acc[mf][nf];
            float2 o0 = make_float2(a4[0] + bs.x, a4[1] + bs.y);
            float2 o1 = make_float2(a4[2] + bs.x, a4[3] + bs.y);
            if (RESID) {
                float2 r0 = *(const float2*)(R + (size_t)row0 * ldr + col);
                float2 r1 = *(const float2*)(R + (size_t)row1 * ldr + col);
                o0.x += r0.x; o0.y += r0.y;
                o1.x += r1.x; o1.y += r1.y;
            }
            *(float2*)(C + (size_t)row0 * N + col) = o0;
            *(float2*)(C + (size_t)row1 * N + col) = o1;
        }
    }
#undef LDG_CHUNK
#undef STS_CHUNK
}

// ------------------------- banded attention ---------------------------------
__global__ __launch_bounds__(256) void band_attn(
    const float* __restrict__ q, const float* __restrict__ k,
    const float* __restrict__ v, float* __restrict__ o)
{
    int t = blockIdx.x, b = blockIdx.y;
    int hh = threadIdx.x >> 5;
    int lane = threadIdx.x & 31;
    const float scale = 0.088388347648318447f;  // 1/sqrt(128)

    size_t base = ((size_t)(b*TT + t))*DD + hh*DH + lane*4;
    float4 qv = *(const float4*)(q + base);

    float s[7];
    float m = -1e30f;
#pragma unroll
    for (int jj = 0; jj < 7; jj++) {
        int j = t - 3 + jj;
        bool ok = (j >= 0) && (j < TT);
        int jc = j < 0 ? 0 : (j > TT-1 ? TT-1 : j);
        size_t kb = ((size_t)(b*TT + jc))*DD + hh*DH + lane*4;
        float4 kv = *(const float4*)(k + kb);
        float d = qv.x*kv.x + qv.y*kv.y + qv.z*kv.z + qv.w*kv.w;
        d += __shfl_xor_sync(0xffffffffu, d, 16);
        d += __shfl_xor_sync(0xffffffffu, d, 8);
        d += __shfl_xor_sync(0xffffffffu, d, 4);
        d += __shfl_xor_sync(0xffffffffu, d, 2);
        d += __shfl_xor_sync(0xffffffffu, d, 1);
        d *= scale;
        s[jj] = ok ? d : -1e30f;
        m = fmaxf(m, s[jj]);
    }
    float sum = 0.f;
#pragma unroll
    for (int jj = 0; jj < 7; jj++) { s[jj] = expf(s[jj] - m); sum += s[jj]; }
    float inv = 1.f / sum;

    float4 acc = make_float4(0.f, 0.f, 0.f, 0.f);
#pragma unroll
    for (int jj = 0; jj < 7; jj++) {
        int j = t - 3 + jj;
        int jc = j < 0 ? 0 : (j > TT-1 ? TT-1 : j);
        size_t vb = ((size_t)(b*TT + jc))*DD + hh*DH + lane*4;
        float4 vv = *(const float4*)(v + vb);
        float p = s[jj] * inv;
        acc.x += p*vv.x; acc.y += p*vv.y; acc.z += p*vv.z; acc.w += p*vv.w;
    }
    *(float4*)(o + base) = acc;
}

// ------------------------- persistent bidirectional GRU ---------------------
__global__ __launch_bounds__(128) void gru_kernel(
    const float* __restrict__ gxf, const float* __restrict__ gxb,
    const float* __restrict__ Whf, const float* __restrict__ Whb,
    const float* __restrict__ bhf, const float* __restrict__ bhb,
    float* __restrict__ out)
{
    extern __shared__ float sm[];
    float* ws = sm;                   // [3*32][260]
    float* hs = sm + 3*32*260;        // [4][264]

    int cta = blockIdx.x;
    int dir = cta >> 6;
    int ug  = (cta >> 3) & 7;
    int bg  = cta & 7;
    int grp = (dir << 3) | bg;
    int tid = threadIdx.x;
    int u   = tid >> 2;
    int bl  = tid & 3;
    int unit  = ug*32 + u;
    int batch = bg*4 + bl;

    const float* Wh = dir ? Whb : Whf;
    const float* bh = dir ? bhb : bhf;
    const float* gx = dir ? gxb : gxf;

    for (int idx = tid; idx < 3*32*256; idx += 128) {
        int g   = idx >> 13;
        int rem = idx & 8191;
        int uu  = rem >> 8;
        int kk  = rem & 255;
        ws[(g*32 + uu)*260 + kk] = Wh[((g << 8) + ug*32 + uu)*256 + kk];
    }
    float br  = bh[unit];
    float bz  = bh[256 + unit];
    float bnn = bh[512 + unit];
    int len = g_len[batch];

    __stcg(&g_hstate[((dir*2 + 0)*BB + batch)*HID + unit], 0.f);
    __threadfence();
    __syncthreads();
    if (tid == 0) atomicAdd(&g_bar[grp], 1u);

    const float* wr = &ws[(0*32 + u)*260];
    const float* wz = &ws[(1*32 + u)*260];
    const float* wn = &ws[(2*32 + u)*260];

    unsigned target = 8u;
    for (int s = 0; s < TT; s++, target += 8u) {
        if (tid == 0) { while (atomicAdd(&g_bar[grp], 0u) < target) {} }
        __syncthreads();
        __threadfence();

        {
            const float* src = &g_hstate[((dir*2 + (s & 1))*BB + bg*4)*HID];
#pragma unroll
            for (int i = 0; i < 8; i++) {
                int idx = tid + i*128;
                int b2 = idx >> 8, k2 = idx & 255;
                hs[b2*264 + k2] = __ldcg(src + b2*256 + k2);
            }
        }
        __syncthreads();

        float4 ar = make_float4(0,0,0,0), az = ar, an = ar;
        const float* hb = &hs[bl*264];
#pragma unroll 8
        for (int kk = 0; kk < 256; kk += 4) {
            float4 h4 = *(const float4*)(hb + kk);
            float4 w1 = *(const float4*)(wr + kk);
            float4 w2 = *(const float4*)(wz + kk);
            float4 w3 = *(const float4*)(wn + kk);
            ar.x += h4.x*w1.x; ar.y += h4.y*w1.y; ar.z += h4.z*w1.z; ar.w += h4.w*w1.w;
            az.x += h4.x*w2.x; az.y += h4.y*w2.y; az.z += h4.z*w2.z; az.w += h4.w*w2.w;
            an.x += h4.x*w3.x; an.y += h4.y*w3.y; an.z += h4.z*w3.z; an.w += h4.w*w3.w;
        }
        float ghr = ar.x + ar.y + ar.z + ar.w;
        float ghz = az.x + az.y + az.z + az.w;
        float ghn = an.x + an.y + an.z + an.w;

        int tt;
        if (dir == 0) tt = s;
        else { int ti = len - 1 - s; tt = ti < 0 ? 0 : ti; }

        const float* gxp = gx + ((size_t)batch*TT + tt)*768;
        float gr = gxp[unit];
        float gz = gxp[256 + unit];
        float gn = gxp[512 + unit];

        float r = 1.f / (1.f + expf(-(gr + ghr + br)));
        float z = 1.f / (1.f + expf(-(gz + ghz + bz)));
        float n = tanhf(gn + r*(ghn + bnn));
        float hp = hs[bl*264 + unit];
        float hn = (1.f - z)*n + z*hp;

        __stcg(&g_hstate[((dir*2 + ((s+1) & 1))*BB + batch)*HID + unit], hn);

        if (s < len) {
            int tout = (dir == 0) ? s : (len - 1 - s);
            float* op = out + ((size_t)batch*TT + tout)*512 + dir*256 + unit;
            *op += hn;
        }
        __syncthreads();
        __threadfence();
        if (tid == 0) atomicAdd(&g_bar[grp], 1u);
    }
}

// ------------------------- launch ------------------------------------------
extern "C" void kernel_launch(void* const* d_in, const int* in_sizes, int n_in,
                              void* d_out, int out_size)
{
    const float* x      = (const float*)d_in[0];
    const int*   mask   = (const int*)  d_in[1];
    const float* W_tran = (const float*)d_in[2];
    const float* b_tran = (const float*)d_in[3];
    const float* Wq     = (const float*)d_in[4];
    const float* bq     = (const float*)d_in[5];
    const float* Wk     = (const float*)d_in[6];
    const float* bk     = (const float*)d_in[7];
    const float* Wv     = (const float*)d_in[8];
    const float* bv     = (const float*)d_in[9];
    const float* Wo     = (const float*)d_in[10];
    const float* bo     = (const float*)d_in[11];
    const float* Wihf   = (const float*)d_in[12];
    const float* Whhf   = (const float*)d_in[13];
    const float* bihf   = (const float*)d_in[14];
    const float* bhhf   = (const float*)d_in[15];
    const float* Wihb   = (const float*)d_in[16];
    const float* Whhb   = (const float*)d_in[17];
    const float* bihb   = (const float*)d_in[18];
    const float* bhhb   = (const float*)d_in[19];
    float* out = (float*)d_out;

    float *hbuf, *qb, *kb, *vb, *aob, *gxfb, *gxbb;
    __nv_bfloat16 *whi, *wlo;
    cudaGetSymbolAddress((void**)&hbuf,  g_h);
    cudaGetSymbolAddress((void**)&qb,    g_q);
    cudaGetSymbolAddress((void**)&kb,    g_k);
    cudaGetSymbolAddress((void**)&vb,    g_v);
    cudaGetSymbolAddress((void**)&aob,   g_ao);
    cudaGetSymbolAddress((void**)&gxfb,  g_gxf);
    cudaGetSymbolAddress((void**)&gxbb,  g_gxb);
    cudaGetSymbolAddress((void**)&whi,   g_Whi);
    cudaGetSymbolAddress((void**)&wlo,   g_Wlo);

    const int smem_gru = (3*32*260 + 4*264) * 4;  // 104,064 B
    cudaFuncSetAttribute(gru_kernel, cudaFuncAttributeMaxDynamicSharedMemorySize, 112*1024);
    cudaFuncSetAttribute(gemm_tc<false>, cudaFuncAttributeMaxDynamicSharedMemorySize, GEMM_SMEM);
    cudaFuncSetAttribute(gemm_tc<true>,  cudaFuncAttributeMaxDynamicSharedMemorySize, GEMM_SMEM);

    prep_kernel<<<BB, 256>>>(mask);

    // weight split/transpose
    {
        dim3 tb(32, 8);
        wsplit_t<<<dim3(512/32, 1536/32), tb>>>(W_tran, whi + OFF_TRAN, wlo + OFF_TRAN, 1536, 512);
        for (int l = 0; l < 2; l++) {
            size_t wo_ = (size_t)l * DD * DD;
            wsplit_t<<<dim3(32, 32), tb>>>(Wq + wo_, whi + OFF_QKVO + (size_t)(l*4+0)*1048576, wlo + OFF_QKVO + (size_t)(l*4+0)*1048576, DD, DD);
            wsplit_t<<<dim3(32, 32), tb>>>(Wk + wo_, whi + OFF_QKVO + (size_t)(l*4+1)*1048576, wlo + OFF_QKVO + (size_t)(l*4+1)*1048576, DD, DD);
            wsplit_t<<<dim3(32, 32), tb>>>(Wv + wo_, whi + OFF_QKVO + (size_t)(l*4+2)*1048576, wlo + OFF_QKVO + (size_t)(l*4+2)*1048576, DD, DD);
            wsplit_t<<<dim3(32, 32), tb>>>(Wo + wo_, whi + OFF_QKVO + (size_t)(l*4+3)*1048576, wlo + OFF_QKVO + (size_t)(l*4+3)*1048576, DD, DD);
        }
        wsplit_c<<<(786432+255)/256, 256>>>(Wihf, whi + OFF_IHF, wlo + OFF_IHF, 786432);
        wsplit_c<<<(786432+255)/256, 256>>>(Wihb, whi + OFF_IHB, wlo + OFF_IHB, 786432);
    }

    // x_face -> out
    gemm_tc<false><<<dim3(4, 64), 256, GEMM_SMEM>>>(
        x + 1024, XF, whi + OFF_TRAN, wlo + OFF_TRAN, b_tran, nullptr, 0, out, 512, 1536);

    for (int l = 0; l < 2; l++) {
        const float* Ain = (l == 0) ? x : hbuf;
        int lda = (l == 0) ? XF : DD;
        size_t bo_ = (size_t)l * DD;
        size_t base = OFF_QKVO + (size_t)(l*4) * 1048576;

        gemm_tc<false><<<dim3(8, 64), 256, GEMM_SMEM>>>(Ain, lda, whi + base + 0*1048576, wlo + base + 0*1048576, bq + bo_, nullptr, 0, qb, DD, DD);
        gemm_tc<false><<<dim3(8, 64), 256, GEMM_SMEM>>>(Ain, lda, whi + base + 1*1048576, wlo + base + 1*1048576, bk + bo_, nullptr, 0, kb, DD, DD);
        gemm_tc<false><<<dim3(8, 64), 256, GEMM_SMEM>>>(Ain, lda, whi + base + 2*1048576, wlo + base + 2*1048576, bv + bo_, nullptr, 0, vb, DD, DD);

        band_attn<<<dim3(TT, BB), 256>>>(qb, kb, vb, aob);

        gemm_tc<true><<<dim3(8, 64), 256, GEMM_SMEM>>>(aob, DD, whi + base + 3*1048576, wlo + base + 3*1048576, bo + bo_, Ain, lda, hbuf, DD, DD);
    }

    // GRU input projections (W_ih already [N][K])
    gemm_tc<false><<<dim3(6, 64), 256, GEMM_SMEM>>>(hbuf, DD, whi + OFF_IHF, wlo + OFF_IHF, bihf, nullptr, 0, gxfb, 768, DD);
    gemm_tc<false><<<dim3(6, 64), 256, GEMM_SMEM>>>(hbuf, DD, whi + OFF_IHB, wlo + OFF_IHB, bihb, nullptr, 0, gxbb, 768, DD);

    // persistent bidirectional GRU, writes out += ys
    gru_kernel<<<128, 128, smem_gru>>>(gxfb, gxbb, Whhf, Whhb, bhhf, bhhb, out);
}

// round 5
// speedup vs baseline: 2.2933x; 1.2209x over previous
#include <cuda_runtime.h>
#include <cuda_bf16.h>
#include <cuda_fp16.h>
#include <math.h>
#include <stdint.h>

// Problem constants
#define BB 32
#define TT 256
#define DD 1024
#define HH 8
#define DH 128
#define HID 256
#define MTOT (BB*TT)          // 8192
#define XF 2560

// ------------------------- scratch (static device memory) -------------------
__device__ float g_h  [MTOT*DD];
__device__ float g_qkv[MTOT*3072];
__device__ float g_ao [MTOT*DD];
__device__ float g_gx [MTOT*1536];
__device__ float g_hstate[2*2*BB*HID];   // [dir][buf][batch][unit]
__device__ unsigned g_bar[16];
__device__ int g_len[BB];
__device__ float g_bias[2*3072 + 1536];

// fp16 weights, [N][K] layout
#define OFF_TRAN 0
#define OFF_QKV(l) (786432 + (size_t)(l)*3145728)
#define OFF_O(l)   (7077888 + (size_t)(l)*1048576)
#define OFF_IH     9175040
#define WH_ELEMS   10747904
__device__ __half g_Wh[WH_ELEMS];

// ------------------------- helpers ------------------------------------------
__device__ __forceinline__ uint32_t smem_u32(const void* p) {
    uint32_t a;
    asm("{ .reg .u64 t; cvta.to.shared.u64 t, %1; cvt.u32.u64 %0, t; }" : "=r"(a) : "l"(p));
    return a;
}
__device__ __forceinline__ void ldsm4(uint32_t* r, uint32_t addr) {
    asm volatile("ldmatrix.sync.aligned.m8n8.x4.shared.b16 {%0,%1,%2,%3}, [%4];"
        : "=r"(r[0]), "=r"(r[1]), "=r"(r[2]), "=r"(r[3]) : "r"(addr));
}
__device__ __forceinline__ void mma_fp16(float* c, const uint32_t* a, uint32_t b0, uint32_t b1) {
    asm volatile(
        "mma.sync.aligned.m16n8k16.row.col.f32.f16.f16.f32 "
        "{%0,%1,%2,%3}, {%4,%5,%6,%7}, {%8,%9}, {%0,%1,%2,%3};"
        : "+f"(c[0]), "+f"(c[1]), "+f"(c[2]), "+f"(c[3])
        : "r"(a[0]), "r"(a[1]), "r"(a[2]), "r"(a[3]), "r"(b0), "r"(b1));
}
__device__ __forceinline__ unsigned ld_acq(const unsigned* p) {
    unsigned v;
    asm volatile("ld.acquire.gpu.global.u32 %0, [%1];" : "=r"(v) : "l"(p) : "memory");
    return v;
}

// ------------------------- prep: lengths + barrier reset --------------------
__global__ void prep_kernel(const int* __restrict__ mask) {
    int b = blockIdx.x;
    __shared__ int red[256];
    red[threadIdx.x] = mask[b*TT + threadIdx.x];
    __syncthreads();
    for (int st = 128; st > 0; st >>= 1) {
        if (threadIdx.x < st) red[threadIdx.x] += red[threadIdx.x + st];
        __syncthreads();
    }
    if (threadIdx.x == 0) g_len[b] = red[0];
    if (b == 0 && threadIdx.x < 16) g_bar[threadIdx.x] = 0u;
}

// ------------------------- bias packing --------------------------------------
__global__ void pack_bias(const float* __restrict__ bq, const float* __restrict__ bk,
                          const float* __restrict__ bv, const float* __restrict__ bihf,
                          const float* __restrict__ bihb) {
    int idx = blockIdx.x * 256 + threadIdx.x;
    if (idx < 6144) {
        int l = idx / 3072, j = idx % 3072;
        float v;
        if (j < 1024)      v = bq[l*1024 + j];
        else if (j < 2048) v = bk[l*1024 + j - 1024];
        else               v = bv[l*1024 + j - 2048];
        g_bias[idx] = v;
    } else if (idx < 7680) {
        int j = idx - 6144;
        g_bias[idx] = (j < 768) ? bihf[j] : bihb[j - 768];
    }
}

// ------------------------- weight transpose / convert to fp16 ---------------
// W: [K][N] row-major -> out: [N][K] fp16
__global__ __launch_bounds__(256) void wtran_h(
    const float* __restrict__ W, __half* __restrict__ out, int K, int N)
{
    __shared__ float ts[32][33];
    int tx = threadIdx.x, ty = threadIdx.y;
    int n0 = blockIdx.x * 32, k0 = blockIdx.y * 32;
#pragma unroll
    for (int i = 0; i < 4; i++)
        ts[ty + i*8][tx] = W[(size_t)(k0 + ty + i*8) * N + n0 + tx];
    __syncthreads();
#pragma unroll
    for (int i = 0; i < 4; i++) {
        int n = n0 + ty + i*8, k = k0 + tx;
        out[(size_t)n * K + k] = __float2half_rn(ts[tx][ty + i*8]);
    }
}

// W already [N][K]: straight convert
__global__ __launch_bounds__(256) void wconv_h(
    const float* __restrict__ W, __half* __restrict__ out, int total)
{
    int idx = blockIdx.x * 256 + threadIdx.x;
    if (idx < total) out[idx] = __float2half_rn(W[idx]);
}

// ------------------------- HMMA fp16x2 GEMM ---------------------------------
// C[M,N] = A[M,K](fp32, split hi/lo fp16) * B[N,K](fp16)^T + bias (+R)
// grid (N/128, M/128), 256 threads (8 warps: 4m x 2n), K % 32 == 0.
#define TILEB 10240                     // 128 rows * 40 halfs * 2B
#define SM_A_HI 0
#define SM_A_LO TILEB
#define SM_B    (2*TILEB)
#define STAGE_BYTES (3*TILEB)           // 30720
#define GEMM_SMEM (2*STAGE_BYTES)       // 61440

template<bool RESID>
__global__ __launch_bounds__(256) void gemm_tc(
    const float* __restrict__ A, int lda,
    const __half* __restrict__ B,
    const float* __restrict__ bias,
    const float* __restrict__ R, int ldr,
    float* __restrict__ C, int N, int K)
{
    extern __shared__ char smem[];
    uint32_t sb = smem_u32(smem);
    int tid = threadIdx.x;
    int lane = tid & 31;
    int wid = tid >> 5;
    int warp_m = wid & 3;      // 0..3
    int warp_n = wid >> 2;     // 0..1
    int bn = blockIdx.x * 128, bm = blockIdx.y * 128;

    float acc[2][8][4];
#pragma unroll
    for (int a = 0; a < 2; a++)
#pragma unroll
        for (int b = 0; b < 8; b++)
#pragma unroll
            for (int c = 0; c < 4; c++) acc[a][b][c] = 0.f;

    float4 aReg[4];
    uint4  bReg[2];

#define LDG_CHUNK(k0)                                                          \
    {                                                                          \
        _Pragma("unroll")                                                      \
        for (int i = 0; i < 4; i++) {                                          \
            int linear = tid + i * 256;                                        \
            int row = linear >> 3, c4 = (linear & 7) * 4;                      \
            aReg[i] = *(const float4*)(A + (size_t)(bm + row) * lda + (k0) + c4);\
        }                                                                      \
        _Pragma("unroll")                                                      \
        for (int i = 0; i < 2; i++) {                                          \
            int linear = tid + i * 256;                                        \
            int row = linear >> 2, c8 = (linear & 3) * 8;                      \
            bReg[i] = *(const uint4*)(B + (size_t)(bn + row) * K + (k0) + c8); \
        }                                                                      \
    }

#define STS_CHUNK(buf)                                                         \
    {                                                                          \
        char* base = smem + (buf) * STAGE_BYTES;                               \
        _Pragma("unroll")                                                      \
        for (int i = 0; i < 4; i++) {                                          \
            int linear = tid + i * 256;                                        \
            int row = linear >> 3, c4 = (linear & 7) * 4;                      \
            float4 f = aReg[i];                                                \
            __half2 h01 = __floats2half2_rn(f.x, f.y);                         \
            __half2 h23 = __floats2half2_rn(f.z, f.w);                         \
            __half2 l01 = __floats2half2_rn(                                   \
                f.x - __half2float(__low2half(h01)),                           \
                f.y - __half2float(__high2half(h01)));                         \
            __half2 l23 = __floats2half2_rn(                                   \
                f.z - __half2float(__low2half(h23)),                           \
                f.w - __half2float(__high2half(h23)));                         \
            uint32_t off = row * 80 + c4 * 2;                                  \
            uint2 uh, ul;                                                      \
            uh.x = *reinterpret_cast<uint32_t*>(&h01);                         \
            uh.y = *reinterpret_cast<uint32_t*>(&h23);                         \
            ul.x = *reinterpret_cast<uint32_t*>(&l01);                         \
            ul.y = *reinterpret_cast<uint32_t*>(&l23);                         \
            *(uint2*)(base + SM_A_HI + off) = uh;                              \
            *(uint2*)(base + SM_A_LO + off) = ul;                              \
        }                                                                      \
        _Pragma("unroll")                                                      \
        for (int i = 0; i < 2; i++) {                                          \
            int linear = tid + i * 256;                                        \
            int row = linear >> 2, c8 = (linear & 3) * 8;                      \
            uint32_t off = row * 80 + c8 * 2;                                  \
            *(uint4*)(base + SM_B + off) = bReg[i];                            \
        }                                                                      \
    }

    const int NC = K / 32;
    LDG_CHUNK(0);
    STS_CHUNK(0);
    __syncthreads();

    for (int ch = 0; ch < NC; ch++) {
        int nxt = ch + 1;
        if (nxt < NC) LDG_CHUNK(nxt * 32);

        uint32_t sbase = sb + (ch & 1) * STAGE_BYTES;
#pragma unroll
        for (int ks = 0; ks < 2; ks++) {
            int kofs = ks * 32;   // bytes (16 halfs)
            uint32_t ah[2][4], al[2][4];
#pragma unroll
            for (int mf = 0; mf < 2; mf++) {
                uint32_t row = warp_m * 32 + mf * 16 + (lane & 15);
                uint32_t addr = sbase + SM_A_HI + row * 80 + kofs + ((lane >> 4) * 16);
                ldsm4(ah[mf], addr);
                ldsm4(al[mf], addr + TILEB);   // A_lo
            }
#pragma unroll
            for (int np = 0; np < 4; np++) {
                uint32_t rown = warp_n * 64 + np * 16 + (lane & 7) + ((lane >> 4) << 3);
                uint32_t addr = sbase + SM_B + rown * 80 + kofs + (((lane >> 3) & 1) * 16);
                uint32_t b[4];
                ldsm4(b, addr);
#pragma unroll
                for (int mf = 0; mf < 2; mf++) {
                    mma_fp16(acc[mf][np*2],   ah[mf], b[0], b[1]);
                    mma_fp16(acc[mf][np*2],   al[mf], b[0], b[1]);
                    mma_fp16(acc[mf][np*2+1], ah[mf], b[2], b[3]);
                    mma_fp16(acc[mf][np*2+1], al[mf], b[2], b[3]);
                }
            }
        }

        if (nxt < NC) STS_CHUNK(nxt & 1);
        __syncthreads();
    }

    // ---- epilogue ----
#pragma unroll
    for (int mf = 0; mf < 2; mf++) {
        int row0 = bm + warp_m * 32 + mf * 16 + (lane >> 2);
        int row1 = row0 + 8;
#pragma unroll
        for (int nf = 0; nf < 8; nf++) {
            int col = bn + warp_n * 64 + nf * 8 + (lane & 3) * 2;
            float2 bs = *(const float2*)(bias + col);
            float* a4 = acc[mf][nf];
            float2 o0 = make_float2(a4[0] + bs.x, a4[1] + bs.y);
            float2 o1 = make_float2(a4[2] + bs.x, a4[3] + bs.y);
            if (RESID) {
                float2 r0 = *(const float2*)(R + (size_t)row0 * ldr + col);
                float2 r1 = *(const float2*)(R + (size_t)row1 * ldr + col);
                o0.x += r0.x; o0.y += r0.y;
                o1.x += r1.x; o1.y += r1.y;
            }
            *(float2*)(C + (size_t)row0 * N + col) = o0;
            *(float2*)(C + (size_t)row1 * N + col) = o1;
        }
    }
#undef LDG_CHUNK
#undef STS_CHUNK
}

// ------------------------- banded attention ---------------------------------
// reads fused qkv buffer [M][3072] (q|k|v), writes g_ao [M][1024]
__global__ __launch_bounds__(256) void band_attn(
    const float* __restrict__ qkv, float* __restrict__ o)
{
    int t = blockIdx.x, b = blockIdx.y;
    int hh = threadIdx.x >> 5;
    int lane = threadIdx.x & 31;
    const float scale = 0.088388347648318447f;  // 1/sqrt(128)

    size_t qb = ((size_t)(b*TT + t))*3072 + hh*DH + lane*4;
    float4 qv = *(const float4*)(qkv + qb);

    float s[7];
    float m = -1e30f;
#pragma unroll
    for (int jj = 0; jj < 7; jj++) {
        int j = t - 3 + jj;
        bool ok = (j >= 0) && (j < TT);
        int jc = j < 0 ? 0 : (j > TT-1 ? TT-1 : j);
        size_t kb = ((size_t)(b*TT + jc))*3072 + 1024 + hh*DH + lane*4;
        float4 kv = *(const float4*)(qkv + kb);
        float d = qv.x*kv.x + qv.y*kv.y + qv.z*kv.z + qv.w*kv.w;
        d += __shfl_xor_sync(0xffffffffu, d, 16);
        d += __shfl_xor_sync(0xffffffffu, d, 8);
        d += __shfl_xor_sync(0xffffffffu, d, 4);
        d += __shfl_xor_sync(0xffffffffu, d, 2);
        d += __shfl_xor_sync(0xffffffffu, d, 1);
        d *= scale;
        s[jj] = ok ? d : -1e30f;
        m = fmaxf(m, s[jj]);
    }
    float sum = 0.f;
#pragma unroll
    for (int jj = 0; jj < 7; jj++) { s[jj] = expf(s[jj] - m); sum += s[jj]; }
    float inv = 1.f / sum;

    float4 acc = make_float4(0.f, 0.f, 0.f, 0.f);
#pragma unroll
    for (int jj = 0; jj < 7; jj++) {
        int j = t - 3 + jj;
        int jc = j < 0 ? 0 : (j > TT-1 ? TT-1 : j);
        size_t vb = ((size_t)(b*TT + jc))*3072 + 2048 + hh*DH + lane*4;
        float4 vv = *(const float4*)(qkv + vb);
        float p = s[jj] * inv;
        acc.x += p*vv.x; acc.y += p*vv.y; acc.z += p*vv.z; acc.w += p*vv.w;
    }
    *(float4*)(o + ((size_t)(b*TT + t))*DD + hh*DH + lane*4) = acc;
}

// ------------------------- persistent bidirectional GRU ---------------------
// 128 CTAs: dir(2) x unit-group(8, 32 units) x batch-group(8, 4 batches)
__global__ __launch_bounds__(128) void gru_kernel(
    const float* __restrict__ gx,
    const float* __restrict__ Whf, const float* __restrict__ Whb,
    const float* __restrict__ bhf, const float* __restrict__ bhb,
    float* __restrict__ out)
{
    extern __shared__ float sm[];
    float* ws = sm;                   // [3*32][260]
    float* hs = sm + 3*32*260;        // [4][264]

    int cta = blockIdx.x;
    int dir = cta >> 6;
    int ug  = (cta >> 3) & 7;
    int bg  = cta & 7;
    int grp = (dir << 3) | bg;
    int tid = threadIdx.x;
    int u   = tid >> 2;
    int bl  = tid & 3;
    int unit  = ug*32 + u;
    int batch = bg*4 + bl;

    const float* Wh = dir ? Whb : Whf;
    const float* bh = dir ? bhb : bhf;

    for (int idx = tid; idx < 3*32*256; idx += 128) {
        int g   = idx >> 13;
        int rem = idx & 8191;
        int uu  = rem >> 8;
        int kk  = rem & 255;
        ws[(g*32 + uu)*260 + kk] = Wh[((g << 8) + ug*32 + uu)*256 + kk];
    }
    float br  = bh[unit];
    float bz  = bh[256 + unit];
    float bnn = bh[512 + unit];
    int len = g_len[batch];

    __stcg(&g_hstate[((dir*2 + 0)*BB + batch)*HID + unit], 0.f);
    __threadfence();
    __syncthreads();
    if (tid == 0) atomicAdd(&g_bar[grp], 1u);

    const float* wr = &ws[(0*32 + u)*260];
    const float* wz = &ws[(1*32 + u)*260];
    const float* wn = &ws[(2*32 + u)*260];

    unsigned target = 8u;
    for (int s = 0; s < TT; s++, target += 8u) {
        // gx loads do not depend on h: issue before the barrier spin
        int tt;
        if (dir == 0) tt = s;
        else { int ti = len - 1 - s; tt = ti < 0 ? 0 : ti; }
        const float* gxp = gx + ((size_t)batch*TT + tt)*1536 + dir*768;
        float gr = gxp[unit];
        float gz = gxp[256 + unit];
        float gn = gxp[512 + unit];

        if (tid == 0) { while (ld_acq(&g_bar[grp]) < target) {} }
        __syncthreads();
        __threadfence();

        {
            const float* src = &g_hstate[((dir*2 + (s & 1))*BB + bg*4)*HID];
#pragma unroll
            for (int i = 0; i < 8; i++) {
                int idx = tid + i*128;
                int b2 = idx >> 8, k2 = idx & 255;
                hs[b2*264 + k2] = __ldcg(src + b2*256 + k2);
            }
        }
        __syncthreads();

        float4 ar = make_float4(0,0,0,0), az = ar, an = ar;
        const float* hb = &hs[bl*264];
#pragma unroll 8
        for (int kk = 0; kk < 256; kk += 4) {
            float4 h4 = *(const float4*)(hb + kk);
            float4 w1 = *(const float4*)(wr + kk);
            float4 w2 = *(const float4*)(wz + kk);
            float4 w3 = *(const float4*)(wn + kk);
            ar.x += h4.x*w1.x; ar.y += h4.y*w1.y; ar.z += h4.z*w1.z; ar.w += h4.w*w1.w;
            az.x += h4.x*w2.x; az.y += h4.y*w2.y; az.z += h4.z*w2.z; az.w += h4.w*w2.w;
            an.x += h4.x*w3.x; an.y += h4.y*w3.y; an.z += h4.z*w3.z; an.w += h4.w*w3.w;
        }
        float ghr = ar.x + ar.y + ar.z + ar.w;
        float ghz = az.x + az.y + az.z + az.w;
        float ghn = an.x + an.y + an.z + an.w;

        float r = 1.f / (1.f + expf(-(gr + ghr + br)));
        float z = 1.f / (1.f + expf(-(gz + ghz + bz)));
        float n = tanhf(gn + r*(ghn + bnn));
        float hp = hs[bl*264 + unit];
        float hn = (1.f - z)*n + z*hp;

        __stcg(&g_hstate[((dir*2 + ((s+1) & 1))*BB + batch)*HID + unit], hn);

        if (s < len) {
            int tout = (dir == 0) ? s : (len - 1 - s);
            float* op = out + ((size_t)batch*TT + tout)*512 + dir*256 + unit;
            *op += hn;
        }
        __syncthreads();
        __threadfence();
        if (tid == 0) atomicAdd(&g_bar[grp], 1u);
    }
}

// ------------------------- launch ------------------------------------------
extern "C" void kernel_launch(void* const* d_in, const int* in_sizes, int n_in,
                              void* d_out, int out_size)
{
    const float* x      = (const float*)d_in[0];
    const int*   mask   = (const int*)  d_in[1];
    const float* W_tran = (const float*)d_in[2];
    const float* b_tran = (const float*)d_in[3];
    const float* Wq     = (const float*)d_in[4];
    const float* bq     = (const float*)d_in[5];
    const float* Wk     = (const float*)d_in[6];
    const float* bk     = (const float*)d_in[7];
    const float* Wv     = (const float*)d_in[8];
    const float* bv     = (const float*)d_in[9];
    const float* Wo     = (const float*)d_in[10];
    const float* bo     = (const float*)d_in[11];
    const float* Wihf   = (const float*)d_in[12];
    const float* Whhf   = (const float*)d_in[13];
    const float* bihf   = (const float*)d_in[14];
    const float* bhhf   = (const float*)d_in[15];
    const float* Wihb   = (const float*)d_in[16];
    const float* Whhb   = (const float*)d_in[17];
    const float* bihb   = (const float*)d_in[18];
    const float* bhhb   = (const float*)d_in[19];
    float* out = (float*)d_out;

    float *hbuf, *qkvb, *aob, *gxb;
    __half *wh;
    cudaGetSymbolAddress((void**)&hbuf,  g_h);
    cudaGetSymbolAddress((void**)&qkvb,  g_qkv);
    cudaGetSymbolAddress((void**)&aob,   g_ao);
    cudaGetSymbolAddress((void**)&gxb,   g_gx);
    cudaGetSymbolAddress((void**)&wh,    g_Wh);

    const int smem_gru = (3*32*260 + 4*264) * 4;  // 104,064 B
    cudaFuncSetAttribute(gru_kernel, cudaFuncAttributeMaxDynamicSharedMemorySize, 112*1024);
    cudaFuncSetAttribute(gemm_tc<false>, cudaFuncAttributeMaxDynamicSharedMemorySize, GEMM_SMEM);
    cudaFuncSetAttribute(gemm_tc<true>,  cudaFuncAttributeMaxDynamicSharedMemorySize, GEMM_SMEM);

    prep_kernel<<<BB, 256>>>(mask);
    pack_bias<<<30, 256>>>(bq, bk, bv, bihf, bihb);

    // weight convert/transpose to fp16 [N][K]
    {
        dim3 tb(32, 8);
        wtran_h<<<dim3(512/32, 1536/32), tb>>>(W_tran, wh + OFF_TRAN, 1536, 512);
        for (int l = 0; l < 2; l++) {
            size_t wo_ = (size_t)l * DD * DD;
            wtran_h<<<dim3(32, 32), tb>>>(Wq + wo_, wh + OFF_QKV(l) + 0*1048576, DD, DD);
            wtran_h<<<dim3(32, 32), tb>>>(Wk + wo_, wh + OFF_QKV(l) + 1*1048576, DD, DD);
            wtran_h<<<dim3(32, 32), tb>>>(Wv + wo_, wh + OFF_QKV(l) + 2*1048576, DD, DD);
            wtran_h<<<dim3(32, 32), tb>>>(Wo + wo_, wh + OFF_O(l), DD, DD);
        }
        wconv_h<<<(786432+255)/256, 256>>>(Wihf, wh + OFF_IH, 786432);
        wconv_h<<<(786432+255)/256, 256>>>(Wihb, wh + OFF_IH + 786432, 786432);
    }

    float* biasbuf;
    cudaGetSymbolAddress((void**)&biasbuf, g_bias);

    // x_face -> out
    gemm_tc<false><<<dim3(4, 64), 256, GEMM_SMEM>>>(
        x + 1024, XF, wh + OFF_TRAN, b_tran, nullptr, 0, out, 512, 1536);

    for (int l = 0; l < 2; l++) {
        const float* Ain = (l == 0) ? x : hbuf;
        int lda = (l == 0) ? XF : DD;

        // fused QKV: N = 3072
        gemm_tc<false><<<dim3(24, 64), 256, GEMM_SMEM>>>(
            Ain, lda, wh + OFF_QKV(l), biasbuf + l*3072, nullptr, 0, qkvb, 3072, DD);

        band_attn<<<dim3(TT, BB), 256>>>(qkvb, aob);

        gemm_tc<true><<<dim3(8, 64), 256, GEMM_SMEM>>>(
            aob, DD, wh + OFF_O(l), bo + (size_t)l*DD, Ain, lda, hbuf, DD, DD);
    }

    // fused GRU input projections: N = 1536 (f | b)
    gemm_tc<false><<<dim3(12, 64), 256, GEMM_SMEM>>>(
        hbuf, DD, wh + OFF_IH, biasbuf + 6144, nullptr, 0, gxb, 1536, DD);

    // persistent bidirectional GRU, writes out += ys
    gru_kernel<<<128, 128, smem_gru>>>(gxb, Whhf, Whhb, bhhf, bhhb, out);
}

// round 6
// speedup vs baseline: 2.7707x; 1.2082x over previous
#include <cuda_runtime.h>
#include <cuda_bf16.h>
#include <cuda_fp16.h>
#include <math.h>
#include <stdint.h>

// Problem constants
#define BB 32
#define TT 256
#define DD 1024
#define HH 8
#define DH 128
#define HID 256
#define MTOT (BB*TT)          // 8192
#define XF 2560

// ------------------------- scratch (static device memory) -------------------
__device__ float g_h  [MTOT*DD];
__device__ float g_qkv[MTOT*3072];
__device__ float g_ao [MTOT*DD];
__device__ float g_gx [MTOT*1536];
__device__ float g_hstate[2*2*BB*HID];   // [dir][buf][batch][unit]
__device__ unsigned g_bar[16];
__device__ int g_len[BB];
__device__ float g_bias[2*3072 + 1536];

// fp16 weights, [N][K] layout
#define OFF_TRAN 0
#define OFF_QKV(l) (786432 + (size_t)(l)*3145728)
#define OFF_O(l)   (7077888 + (size_t)(l)*1048576)
#define OFF_IH     9175040
#define WH_ELEMS   10747904
__device__ __half g_Wh[WH_ELEMS];

// ------------------------- helpers ------------------------------------------
__device__ __forceinline__ uint32_t smem_u32(const void* p) {
    uint32_t a;
    asm("{ .reg .u64 t; cvta.to.shared.u64 t, %1; cvt.u32.u64 %0, t; }" : "=r"(a) : "l"(p));
    return a;
}
__device__ __forceinline__ void ldsm4(uint32_t* r, uint32_t addr) {
    asm volatile("ldmatrix.sync.aligned.m8n8.x4.shared.b16 {%0,%1,%2,%3}, [%4];"
        : "=r"(r[0]), "=r"(r[1]), "=r"(r[2]), "=r"(r[3]) : "r"(addr));
}
__device__ __forceinline__ void mma_fp16(float* c, const uint32_t* a, uint32_t b0, uint32_t b1) {
    asm volatile(
        "mma.sync.aligned.m16n8k16.row.col.f32.f16.f16.f32 "
        "{%0,%1,%2,%3}, {%4,%5,%6,%7}, {%8,%9}, {%0,%1,%2,%3};"
        : "+f"(c[0]), "+f"(c[1]), "+f"(c[2]), "+f"(c[3])
        : "r"(a[0]), "r"(a[1]), "r"(a[2]), "r"(a[3]), "r"(b0), "r"(b1));
}
__device__ __forceinline__ unsigned ld_acq(const unsigned* p) {
    unsigned v;
    asm volatile("ld.acquire.gpu.global.u32 %0, [%1];" : "=r"(v) : "l"(p) : "memory");
    return v;
}
__device__ __forceinline__ void red_release(unsigned* p, unsigned v) {
    asm volatile("red.release.gpu.global.add.u32 [%0], %1;" :: "l"(p), "r"(v) : "memory");
}

// ------------------------- prep: lengths + barrier reset --------------------
__global__ void prep_kernel(const int* __restrict__ mask) {
    int b = blockIdx.x;
    __shared__ int red[256];
    red[threadIdx.x] = mask[b*TT + threadIdx.x];
    __syncthreads();
    for (int st = 128; st > 0; st >>= 1) {
        if (threadIdx.x < st) red[threadIdx.x] += red[threadIdx.x + st];
        __syncthreads();
    }
    if (threadIdx.x == 0) g_len[b] = red[0];
    if (b == 0 && threadIdx.x < 16) g_bar[threadIdx.x] = 0u;
}

// ------------------------- bias packing --------------------------------------
__global__ void pack_bias(const float* __restrict__ bq, const float* __restrict__ bk,
                          const float* __restrict__ bv, const float* __restrict__ bihf,
                          const float* __restrict__ bihb) {
    int idx = blockIdx.x * 256 + threadIdx.x;
    if (idx < 6144) {
        int l = idx / 3072, j = idx % 3072;
        float v;
        if (j < 1024)      v = bq[l*1024 + j];
        else if (j < 2048) v = bk[l*1024 + j - 1024];
        else               v = bv[l*1024 + j - 2048];
        g_bias[idx] = v;
    } else if (idx < 7680) {
        int j = idx - 6144;
        g_bias[idx] = (j < 768) ? bihf[j] : bihb[j - 768];
    }
}

// ------------------------- weight transpose / convert to fp16 ---------------
// W: [K][N] row-major -> out: [N][K] fp16
__global__ __launch_bounds__(256) void wtran_h(
    const float* __restrict__ W, __half* __restrict__ out, int K, int N)
{
    __shared__ float ts[32][33];
    int tx = threadIdx.x, ty = threadIdx.y;
    int n0 = blockIdx.x * 32, k0 = blockIdx.y * 32;
#pragma unroll
    for (int i = 0; i < 4; i++)
        ts[ty + i*8][tx] = W[(size_t)(k0 + ty + i*8) * N + n0 + tx];
    __syncthreads();
#pragma unroll
    for (int i = 0; i < 4; i++) {
        int n = n0 + ty + i*8, k = k0 + tx;
        out[(size_t)n * K + k] = __float2half_rn(ts[tx][ty + i*8]);
    }
}

// W already [N][K]: straight convert
__global__ __launch_bounds__(256) void wconv_h(
    const float* __restrict__ W, __half* __restrict__ out, int total)
{
    int idx = blockIdx.x * 256 + threadIdx.x;
    if (idx < total) out[idx] = __float2half_rn(W[idx]);
}

// ------------------------- HMMA fp16 GEMM -----------------------------------
// C[M,N] = A[M,K](fp32 -> fp16 single-rounded) * B[N,K](fp16)^T + bias (+R)
// grid (N/128, M/128), 256 threads (8 warps: 4m x 2n), K % 32 == 0.
#define TILEB 10240                     // 128 rows * 40 halfs * 2B
#define SM_A 0
#define SM_B TILEB
#define STAGE_BYTES (2*TILEB)           // 20480
#define GEMM_SMEM (2*STAGE_BYTES)       // 40960

template<bool RESID>
__global__ __launch_bounds__(256) void gemm_tc(
    const float* __restrict__ A, int lda,
    const __half* __restrict__ B,
    const float* __restrict__ bias,
    const float* __restrict__ R, int ldr,
    float* __restrict__ C, int N, int K)
{
    extern __shared__ char smem[];
    uint32_t sb = smem_u32(smem);
    int tid = threadIdx.x;
    int lane = tid & 31;
    int wid = tid >> 5;
    int warp_m = wid & 3;      // 0..3
    int warp_n = wid >> 2;     // 0..1
    int bn = blockIdx.x * 128, bm = blockIdx.y * 128;

    float acc[2][8][4];
#pragma unroll
    for (int a = 0; a < 2; a++)
#pragma unroll
        for (int b = 0; b < 8; b++)
#pragma unroll
            for (int c = 0; c < 4; c++) acc[a][b][c] = 0.f;

    float4 aReg[4];
    uint4  bReg[2];

#define LDG_CHUNK(k0)                                                          \
    {                                                                          \
        _Pragma("unroll")                                                      \
        for (int i = 0; i < 4; i++) {                                          \
            int linear = tid + i * 256;                                        \
            int row = linear >> 3, c4 = (linear & 7) * 4;                      \
            aReg[i] = *(const float4*)(A + (size_t)(bm + row) * lda + (k0) + c4);\
        }                                                                      \
        _Pragma("unroll")                                                      \
        for (int i = 0; i < 2; i++) {                                          \
            int linear = tid + i * 256;                                        \
            int row = linear >> 2, c8 = (linear & 3) * 8;                      \
            bReg[i] = *(const uint4*)(B + (size_t)(bn + row) * K + (k0) + c8); \
        }                                                                      \
    }

#define STS_CHUNK(buf)                                                         \
    {                                                                          \
        char* base = smem + (buf) * STAGE_BYTES;                               \
        _Pragma("unroll")                                                      \
        for (int i = 0; i < 4; i++) {                                          \
            int linear = tid + i * 256;                                        \
            int row = linear >> 3, c4 = (linear & 7) * 4;                      \
            float4 f = aReg[i];                                                \
            __half2 h01 = __floats2half2_rn(f.x, f.y);                         \
            __half2 h23 = __floats2half2_rn(f.z, f.w);                         \
            uint32_t off = row * 80 + c4 * 2;                                  \
            uint2 uh;                                                          \
            uh.x = *reinterpret_cast<uint32_t*>(&h01);                         \
            uh.y = *reinterpret_cast<uint32_t*>(&h23);                         \
            *(uint2*)(base + SM_A + off) = uh;                                 \
        }                                                                      \
        _Pragma("unroll")                                                      \
        for (int i = 0; i < 2; i++) {                                          \
            int linear = tid + i * 256;                                        \
            int row = linear >> 2, c8 = (linear & 3) * 8;                      \
            uint32_t off = row * 80 + c8 * 2;                                  \
            *(uint4*)(base + SM_B + off) = bReg[i];                            \
        }                                                                      \
    }

    const int NC = K / 32;
    LDG_CHUNK(0);
    STS_CHUNK(0);
    __syncthreads();

    for (int ch = 0; ch < NC; ch++) {
        int nxt = ch + 1;
        if (nxt < NC) LDG_CHUNK(nxt * 32);

        uint32_t sbase = sb + (ch & 1) * STAGE_BYTES;
#pragma unroll
        for (int ks = 0; ks < 2; ks++) {
            int kofs = ks * 32;   // bytes (16 halfs)
            uint32_t ah[2][4];
#pragma unroll
            for (int mf = 0; mf < 2; mf++) {
                uint32_t row = warp_m * 32 + mf * 16 + (lane & 15);
                uint32_t addr = sbase + SM_A + row * 80 + kofs + ((lane >> 4) * 16);
                ldsm4(ah[mf], addr);
            }
#pragma unroll
            for (int np = 0; np < 4; np++) {
                uint32_t rown = warp_n * 64 + np * 16 + (lane & 7) + ((lane >> 4) << 3);
                uint32_t addr = sbase + SM_B + rown * 80 + kofs + (((lane >> 3) & 1) * 16);
                uint32_t b[4];
                ldsm4(b, addr);
#pragma unroll
                for (int mf = 0; mf < 2; mf++) {
                    mma_fp16(acc[mf][np*2],   ah[mf], b[0], b[1]);
                    mma_fp16(acc[mf][np*2+1], ah[mf], b[2], b[3]);
                }
            }
        }

        if (nxt < NC) STS_CHUNK(nxt & 1);
        __syncthreads();
    }

    // ---- epilogue ----
#pragma unroll
    for (int mf = 0; mf < 2; mf++) {
        int row0 = bm + warp_m * 32 + mf * 16 + (lane >> 2);
        int row1 = row0 + 8;
#pragma unroll
        for (int nf = 0; nf < 8; nf++) {
            int col = bn + warp_n * 64 + nf * 8 + (lane & 3) * 2;
            float2 bs = *(const float2*)(bias + col);
            float* a4 = acc[mf][nf];
            float2 o0 = make_float2(a4[0] + bs.x, a4[1] + bs.y);
            float2 o1 = make_float2(a4[2] + bs.x, a4[3] + bs.y);
            if (RESID) {
                float2 r0 = *(const float2*)(R + (size_t)row0 * ldr + col);
                float2 r1 = *(const float2*)(R + (size_t)row1 * ldr + col);
                o0.x += r0.x; o0.y += r0.y;
                o1.x += r1.x; o1.y += r1.y;
            }
            *(float2*)(C + (size_t)row0 * N + col) = o0;
            *(float2*)(C + (size_t)row1 * N + col) = o1;
        }
    }
#undef LDG_CHUNK
#undef STS_CHUNK
}

// ------------------------- banded attention ---------------------------------
// reads fused qkv buffer [M][3072] (q|k|v), writes g_ao [M][1024]
__global__ __launch_bounds__(256) void band_attn(
    const float* __restrict__ qkv, float* __restrict__ o)
{
    int t = blockIdx.x, b = blockIdx.y;
    int hh = threadIdx.x >> 5;
    int lane = threadIdx.x & 31;
    const float scale = 0.088388347648318447f;  // 1/sqrt(128)

    size_t qb = ((size_t)(b*TT + t))*3072 + hh*DH + lane*4;
    float4 qv = *(const float4*)(qkv + qb);

    float s[7];
    float m = -1e30f;
#pragma unroll
    for (int jj = 0; jj < 7; jj++) {
        int j = t - 3 + jj;
        bool ok = (j >= 0) && (j < TT);
        int jc = j < 0 ? 0 : (j > TT-1 ? TT-1 : j);
        size_t kb = ((size_t)(b*TT + jc))*3072 + 1024 + hh*DH + lane*4;
        float4 kv = *(const float4*)(qkv + kb);
        float d = qv.x*kv.x + qv.y*kv.y + qv.z*kv.z + qv.w*kv.w;
        d += __shfl_xor_sync(0xffffffffu, d, 16);
        d += __shfl_xor_sync(0xffffffffu, d, 8);
        d += __shfl_xor_sync(0xffffffffu, d, 4);
        d += __shfl_xor_sync(0xffffffffu, d, 2);
        d += __shfl_xor_sync(0xffffffffu, d, 1);
        d *= scale;
        s[jj] = ok ? d : -1e30f;
        m = fmaxf(m, s[jj]);
    }
    float sum = 0.f;
#pragma unroll
    for (int jj = 0; jj < 7; jj++) { s[jj] = expf(s[jj] - m); sum += s[jj]; }
    float inv = 1.f / sum;

    float4 acc = make_float4(0.f, 0.f, 0.f, 0.f);
#pragma unroll
    for (int jj = 0; jj < 7; jj++) {
        int j = t - 3 + jj;
        int jc = j < 0 ? 0 : (j > TT-1 ? TT-1 : j);
        size_t vb = ((size_t)(b*TT + jc))*3072 + 2048 + hh*DH + lane*4;
        float4 vv = *(const float4*)(qkv + vb);
        float p = s[jj] * inv;
        acc.x += p*vv.x; acc.y += p*vv.y; acc.z += p*vv.z; acc.w += p*vv.w;
    }
    *(float4*)(o + ((size_t)(b*TT + t))*DD + hh*DH + lane*4) = acc;
}

// ------------------------- persistent bidirectional GRU ---------------------
// 128 CTAs: dir(2) x unit-group(8, 32 units) x batch-group(8, 4 batches)
__global__ __launch_bounds__(128) void gru_kernel(
    const float* __restrict__ gx,
    const float* __restrict__ Whf, const float* __restrict__ Whb,
    const float* __restrict__ bhf, const float* __restrict__ bhb,
    float* __restrict__ out)
{
    extern __shared__ float sm[];
    float* ws = sm;                   // [3*32][260]
    float* hs = sm + 3*32*260;        // [4][264]

    int cta = blockIdx.x;
    int dir = cta >> 6;
    int ug  = (cta >> 3) & 7;
    int bg  = cta & 7;
    int grp = (dir << 3) | bg;
    int tid = threadIdx.x;
    int u   = tid >> 2;
    int bl  = tid & 3;
    int unit  = ug*32 + u;
    int batch = bg*4 + bl;

    const float* Wh = dir ? Whb : Whf;
    const float* bh = dir ? bhb : bhf;

    for (int idx = tid; idx < 3*32*256; idx += 128) {
        int g   = idx >> 13;
        int rem = idx & 8191;
        int uu  = rem >> 8;
        int kk  = rem & 255;
        ws[(g*32 + uu)*260 + kk] = Wh[((g << 8) + ug*32 + uu)*256 + kk];
    }
    float br  = bh[unit];
    float bz  = bh[256 + unit];
    float bnn = bh[512 + unit];
    int len = g_len[batch];

    __stcg(&g_hstate[((dir*2 + 0)*BB + batch)*HID + unit], 0.f);
    __syncthreads();
    if (tid == 0) red_release(&g_bar[grp], 1u);

    const float* wr = &ws[(0*32 + u)*260];
    const float* wz = &ws[(1*32 + u)*260];
    const float* wn = &ws[(2*32 + u)*260];

    unsigned target = 8u;
    for (int s = 0; s < TT; s++, target += 8u) {
        // gx loads do not depend on h: issue before the barrier spin
        int tt;
        if (dir == 0) tt = s;
        else { int ti = len - 1 - s; tt = ti < 0 ? 0 : ti; }
        const float* gxp = gx + ((size_t)batch*TT + tt)*1536 + dir*768;
        float gr = gxp[unit];
        float gz = gxp[256 + unit];
        float gn = gxp[512 + unit];

        if (tid == 0) { while (ld_acq(&g_bar[grp]) < target) {} }
        __syncthreads();

        {
            const float* src = &g_hstate[((dir*2 + (s & 1))*BB + bg*4)*HID];
#pragma unroll
            for (int i = 0; i < 8; i++) {
                int idx = tid + i*128;
                int b2 = idx >> 8, k2 = idx & 255;
                hs[b2*264 + k2] = __ldcg(src + b2*256 + k2);
            }
        }
        __syncthreads();

        float4 ar = make_float4(0,0,0,0), az = ar, an = ar;
        const float* hb = &hs[bl*264];
#pragma unroll 8
        for (int kk = 0; kk < 256; kk += 4) {
            float4 h4 = *(const float4*)(hb + kk);
            float4 w1 = *(const float4*)(wr + kk);
            float4 w2 = *(const float4*)(wz + kk);
            float4 w3 = *(const float4*)(wn + kk);
            ar.x += h4.x*w1.x; ar.y += h4.y*w1.y; ar.z += h4.z*w1.z; ar.w += h4.w*w1.w;
            az.x += h4.x*w2.x; az.y += h4.y*w2.y; az.z += h4.z*w2.z; az.w += h4.w*w2.w;
            an.x += h4.x*w3.x; an.y += h4.y*w3.y; an.z += h4.z*w3.z; an.w += h4.w*w3.w;
        }
        float ghr = ar.x + ar.y + ar.z + ar.w;
        float ghz = az.x + az.y + az.z + az.w;
        float ghn = an.x + an.y + an.z + an.w;

        float r = 1.f / (1.f + expf(-(gr + ghr + br)));
        float z = 1.f / (1.f + expf(-(gz + ghz + bz)));
        float n = tanhf(gn + r*(ghn + bnn));
        float hp = hs[bl*264 + unit];
        float hn = (1.f - z)*n + z*hp;

        __stcg(&g_hstate[((dir*2 + ((s+1) & 1))*BB + batch)*HID + unit], hn);

        if (s < len) {
            int tout = (dir == 0) ? s : (len - 1 - s);
            float* op = out + ((size_t)batch*TT + tout)*512 + dir*256 + unit;
            *op += hn;
        }
        __syncthreads();
        if (tid == 0) red_release(&g_bar[grp], 1u);
    }
}

// ------------------------- launch ------------------------------------------
extern "C" void kernel_launch(void* const* d_in, const int* in_sizes, int n_in,
                              void* d_out, int out_size)
{
    const float* x      = (const float*)d_in[0];
    const int*   mask   = (const int*)  d_in[1];
    const float* W_tran = (const float*)d_in[2];
    const float* b_tran = (const float*)d_in[3];
    const float* Wq     = (const float*)d_in[4];
    const float* bq     = (const float*)d_in[5];
    const float* Wk     = (const float*)d_in[6];
    const float* bk     = (const float*)d_in[7];
    const float* Wv     = (const float*)d_in[8];
    const float* bv     = (const float*)d_in[9];
    const float* Wo     = (const float*)d_in[10];
    const float* bo     = (const float*)d_in[11];
    const float* Wihf   = (const float*)d_in[12];
    const float* Whhf   = (const float*)d_in[13];
    const float* bihf   = (const float*)d_in[14];
    const float* bhhf   = (const float*)d_in[15];
    const float* Wihb   = (const float*)d_in[16];
    const float* Whhb   = (const float*)d_in[17];
    const float* bihb   = (const float*)d_in[18];
    const float* bhhb   = (const float*)d_in[19];
    float* out = (float*)d_out;

    float *hbuf, *qkvb, *aob, *gxb;
    __half *wh;
    cudaGetSymbolAddress((void**)&hbuf,  g_h);
    cudaGetSymbolAddress((void**)&qkvb,  g_qkv);
    cudaGetSymbolAddress((void**)&aob,   g_ao);
    cudaGetSymbolAddress((void**)&gxb,   g_gx);
    cudaGetSymbolAddress((void**)&wh,    g_Wh);

    const int smem_gru = (3*32*260 + 4*264) * 4;  // 104,064 B
    cudaFuncSetAttribute(gru_kernel, cudaFuncAttributeMaxDynamicSharedMemorySize, 112*1024);
    cudaFuncSetAttribute(gemm_tc<false>, cudaFuncAttributeMaxDynamicSharedMemorySize, GEMM_SMEM);
    cudaFuncSetAttribute(gemm_tc<true>,  cudaFuncAttributeMaxDynamicSharedMemorySize, GEMM_SMEM);

    prep_kernel<<<BB, 256>>>(mask);
    pack_bias<<<30, 256>>>(bq, bk, bv, bihf, bihb);

    // weight convert/transpose to fp16 [N][K]
    {
        dim3 tb(32, 8);
        wtran_h<<<dim3(512/32, 1536/32), tb>>>(W_tran, wh + OFF_TRAN, 1536, 512);
        for (int l = 0; l < 2; l++) {
            size_t wo_ = (size_t)l * DD * DD;
            wtran_h<<<dim3(32, 32), tb>>>(Wq + wo_, wh + OFF_QKV(l) + 0*1048576, DD, DD);
            wtran_h<<<dim3(32, 32), tb>>>(Wk + wo_, wh + OFF_QKV(l) + 1*1048576, DD, DD);
            wtran_h<<<dim3(32, 32), tb>>>(Wv + wo_, wh + OFF_QKV(l) + 2*1048576, DD, DD);
            wtran_h<<<dim3(32, 32), tb>>>(Wo + wo_, wh + OFF_O(l), DD, DD);
        }
        wconv_h<<<(786432+255)/256, 256>>>(Wihf, wh + OFF_IH, 786432);
        wconv_h<<<(786432+255)/256, 256>>>(Wihb, wh + OFF_IH + 786432, 786432);
    }

    float* biasbuf;
    cudaGetSymbolAddress((void**)&biasbuf, g_bias);

    // x_face -> out
    gemm_tc<false><<<dim3(4, 64), 256, GEMM_SMEM>>>(
        x + 1024, XF, wh + OFF_TRAN, b_tran, nullptr, 0, out, 512, 1536);

    for (int l = 0; l < 2; l++) {
        const float* Ain = (l == 0) ? x : hbuf;
        int lda = (l == 0) ? XF : DD;

        // fused QKV: N = 3072
        gemm_tc<false><<<dim3(24, 64), 256, GEMM_SMEM>>>(
            Ain, lda, wh + OFF_QKV(l), biasbuf + l*3072, nullptr, 0, qkvb, 3072, DD);

        band_attn<<<dim3(TT, BB), 256>>>(qkvb, aob);

        gemm_tc<true><<<dim3(8, 64), 256, GEMM_SMEM>>>(
            aob, DD, wh + OFF_O(l), bo + (size_t)l*DD, Ain, lda, hbuf, DD, DD);
    }

    // fused GRU input projections: N = 1536 (f | b)
    gemm_tc<false><<<dim3(12, 64), 256, GEMM_SMEM>>>(
        hbuf, DD, wh + OFF_IH, biasbuf + 6144, nullptr, 0, gxb, 1536, DD);

    // persistent bidirectional GRU, writes out += ys
    gru_kernel<<<128, 128, smem_gru>>>(gxb, Whhf, Whhb, bhhf, bhhb, out);
}

// round 7
// speedup vs baseline: 3.4086x; 1.2302x over previous
#include <cuda_runtime.h>
#include <cuda_fp16.h>
#include <math.h>
#include <stdint.h>

// Problem constants
#define BB 32
#define TT 256
#define DD 1024
#define HH 8
#define DH 128
#define HID 256
#define MTOT (BB*TT)          // 8192
#define XF 2560

// ------------------------- scratch (static device memory) -------------------
__device__ float  g_h  [MTOT*DD];        // fp32 residual stream
__device__ __half g_hh [MTOT*DD];        // fp16 copy of h
__device__ __half g_xh [MTOT*XF];        // fp16 copy of x
__device__ __half g_qkv[MTOT*3072];      // fp16 qkv
__device__ __half g_ao [MTOT*DD];        // fp16 attention out
__device__ float  g_gx [MTOT*1536];      // fp32 GRU input projections
__device__ float  g_hstate[2*2*BB*HID];  // [dir][buf][batch][unit]
__device__ unsigned g_bar[16];
__device__ int g_len[BB];
__device__ float g_bias[2*3072 + 1536];

// fp16 weights, [N][K] layout
#define OFF_TRAN 0
#define OFF_QKV(l) (786432 + (size_t)(l)*3145728)
#define OFF_O(l)   (7077888 + (size_t)(l)*1048576)
#define OFF_IH     9175040
#define WH_ELEMS   10747904
__device__ __half g_Wh[WH_ELEMS];

// ------------------------- helpers ------------------------------------------
__device__ __forceinline__ uint32_t smem_u32(const void* p) {
    uint32_t a;
    asm("{ .reg .u64 t; cvta.to.shared.u64 t, %1; cvt.u32.u64 %0, t; }" : "=r"(a) : "l"(p));
    return a;
}
__device__ __forceinline__ void ldsm4(uint32_t* r, uint32_t addr) {
    asm volatile("ldmatrix.sync.aligned.m8n8.x4.shared.b16 {%0,%1,%2,%3}, [%4];"
        : "=r"(r[0]), "=r"(r[1]), "=r"(r[2]), "=r"(r[3]) : "r"(addr));
}
__device__ __forceinline__ void mma_fp16(float* c, const uint32_t* a, uint32_t b0, uint32_t b1) {
    asm volatile(
        "mma.sync.aligned.m16n8k16.row.col.f32.f16.f16.f32 "
        "{%0,%1,%2,%3}, {%4,%5,%6,%7}, {%8,%9}, {%0,%1,%2,%3};"
        : "+f"(c[0]), "+f"(c[1]), "+f"(c[2]), "+f"(c[3])
        : "r"(a[0]), "r"(a[1]), "r"(a[2]), "r"(a[3]), "r"(b0), "r"(b1));
}
__device__ __forceinline__ unsigned ld_acq(const unsigned* p) {
    unsigned v;
    asm volatile("ld.acquire.gpu.global.u32 %0, [%1];" : "=r"(v) : "l"(p) : "memory");
    return v;
}
__device__ __forceinline__ void red_release(unsigned* p, unsigned v) {
    asm volatile("red.release.gpu.global.add.u32 [%0], %1;" :: "l"(p), "r"(v) : "memory");
}

// ------------------------- prep: lengths + barrier reset --------------------
__global__ void prep_kernel(const int* __restrict__ mask) {
    int b = blockIdx.x;
    __shared__ int red[256];
    red[threadIdx.x] = mask[b*TT + threadIdx.x];
    __syncthreads();
    for (int st = 128; st > 0; st >>= 1) {
        if (threadIdx.x < st) red[threadIdx.x] += red[threadIdx.x + st];
        __syncthreads();
    }
    if (threadIdx.x == 0) g_len[b] = red[0];
    if (b == 0 && threadIdx.x < 16) g_bar[threadIdx.x] = 0u;
}

// ------------------------- bias packing --------------------------------------
__global__ void pack_bias(const float* __restrict__ bq, const float* __restrict__ bk,
                          const float* __restrict__ bv, const float* __restrict__ bihf,
                          const float* __restrict__ bihb) {
    int idx = blockIdx.x * 256 + threadIdx.x;
    if (idx < 6144) {
        int l = idx / 3072, j = idx % 3072;
        float v;
        if (j < 1024)      v = bq[l*1024 + j];
        else if (j < 2048) v = bk[l*1024 + j - 1024];
        else               v = bv[l*1024 + j - 2048];
        g_bias[idx] = v;
    } else if (idx < 7680) {
        int j = idx - 6144;
        g_bias[idx] = (j < 768) ? bihf[j] : bihb[j - 768];
    }
}

// ------------------------- x -> fp16 convert (vectorized) -------------------
__global__ __launch_bounds__(256) void xconv(
    const float* __restrict__ x, __half* __restrict__ xh, int total4)
{
    int idx = blockIdx.x * 256 + threadIdx.x;
    if (idx < total4) {
        float4 f = ((const float4*)x)[idx];
        __half2 h01 = __floats2half2_rn(f.x, f.y);
        __half2 h23 = __floats2half2_rn(f.z, f.w);
        uint2 u;
        u.x = *reinterpret_cast<uint32_t*>(&h01);
        u.y = *reinterpret_cast<uint32_t*>(&h23);
        ((uint2*)xh)[idx] = u;
    }
}

// ------------------------- weight transpose / convert to fp16 ---------------
// W: [K][N] row-major -> out: [N][K] fp16
__global__ __launch_bounds__(256) void wtran_h(
    const float* __restrict__ W, __half* __restrict__ out, int K, int N)
{
    __shared__ float ts[32][33];
    int tx = threadIdx.x, ty = threadIdx.y;
    int n0 = blockIdx.x * 32, k0 = blockIdx.y * 32;
#pragma unroll
    for (int i = 0; i < 4; i++)
        ts[ty + i*8][tx] = W[(size_t)(k0 + ty + i*8) * N + n0 + tx];
    __syncthreads();
#pragma unroll
    for (int i = 0; i < 4; i++) {
        int n = n0 + ty + i*8, k = k0 + tx;
        out[(size_t)n * K + k] = __float2half_rn(ts[tx][ty + i*8]);
    }
}

// W already [N][K]: straight convert
__global__ __launch_bounds__(256) void wconv_h(
    const float* __restrict__ W, __half* __restrict__ out, int total)
{
    int idx = blockIdx.x * 256 + threadIdx.x;
    if (idx < total) out[idx] = __float2half_rn(W[idx]);
}

// ------------------------- HMMA fp16 GEMM -----------------------------------
// C = A[M,K](fp16) * B[N,K](fp16)^T + bias (+R fp32)
// outputs: Cf (fp32) if WF, Ch (fp16) if WH
// grid (N/128, M/128), 256 threads (8 warps: 4m x 2n), K % 64 == 0.
#define TILEPB 18432                    // 128 rows * 72 halfs * 2B
#define SM_A 0
#define SM_B TILEPB
#define STAGE_BYTES (2*TILEPB)          // 36864
#define GEMM_SMEM (2*STAGE_BYTES)       // 73728

template<bool RESID, bool WF, bool WH>
__global__ __launch_bounds__(256) void gemm_h(
    const __half* __restrict__ A, int lda,
    const __half* __restrict__ B,
    const float* __restrict__ bias,
    const float* __restrict__ R, int ldr,
    float* __restrict__ Cf, __half* __restrict__ Ch,
    int N, int K)
{
    extern __shared__ char smem[];
    uint32_t sb = smem_u32(smem);
    int tid = threadIdx.x;
    int lane = tid & 31;
    int wid = tid >> 5;
    int warp_m = wid & 3;      // 0..3
    int warp_n = wid >> 2;     // 0..1
    int bn = blockIdx.x * 128, bm = blockIdx.y * 128;

    float acc[2][8][4];
#pragma unroll
    for (int a = 0; a < 2; a++)
#pragma unroll
        for (int b = 0; b < 8; b++)
#pragma unroll
            for (int c = 0; c < 4; c++) acc[a][b][c] = 0.f;

    uint4 aReg[4], bReg[4];

#define LDG_CHUNK(k0)                                                          \
    {                                                                          \
        _Pragma("unroll")                                                      \
        for (int i = 0; i < 4; i++) {                                          \
            int linear = tid + i * 256;                                        \
            int row = linear >> 3, c8 = (linear & 7) * 8;                      \
            aReg[i] = *(const uint4*)(A + (size_t)(bm + row) * lda + (k0) + c8);\
            bReg[i] = *(const uint4*)(B + (size_t)(bn + row) * K + (k0) + c8); \
        }                                                                      \
    }

#define STS_CHUNK(buf)                                                         \
    {                                                                          \
        char* base = smem + (buf) * STAGE_BYTES;                               \
        _Pragma("unroll")                                                      \
        for (int i = 0; i < 4; i++) {                                          \
            int linear = tid + i * 256;                                        \
            int row = linear >> 3, c8 = (linear & 7) * 8;                      \
            uint32_t off = row * 144 + c8 * 2;                                 \
            *(uint4*)(base + SM_A + off) = aReg[i];                            \
            *(uint4*)(base + SM_B + off) = bReg[i];                            \
        }                                                                      \
    }

    const int NC = K / 64;
    LDG_CHUNK(0);
    STS_CHUNK(0);
    __syncthreads();

    for (int ch = 0; ch < NC; ch++) {
        int nxt = ch + 1;
        if (nxt < NC) LDG_CHUNK(nxt * 64);

        uint32_t sbase = sb + (ch & 1) * STAGE_BYTES;
#pragma unroll
        for (int ks = 0; ks < 4; ks++) {
            int kofs = ks * 32;   // bytes (16 halfs)
            uint32_t ah[2][4];
#pragma unroll
            for (int mf = 0; mf < 2; mf++) {
                uint32_t row = warp_m * 32 + mf * 16 + (lane & 15);
                uint32_t addr = sbase + SM_A + row * 144 + kofs + ((lane >> 4) * 16);
                ldsm4(ah[mf], addr);
            }
#pragma unroll
            for (int np = 0; np < 4; np++) {
                uint32_t rown = warp_n * 64 + np * 16 + (lane & 7) + ((lane >> 4) << 3);
                uint32_t addr = sbase + SM_B + rown * 144 + kofs + (((lane >> 3) & 1) * 16);
                uint32_t b[4];
                ldsm4(b, addr);
#pragma unroll
                for (int mf = 0; mf < 2; mf++) {
                    mma_fp16(acc[mf][np*2],   ah[mf], b[0], b[1]);
                    mma_fp16(acc[mf][np*2+1], ah[mf], b[2], b[3]);
                }
            }
        }

        if (nxt < NC) STS_CHUNK(nxt & 1);
        __syncthreads();
    }

    // ---- epilogue ----
#pragma unroll
    for (int mf = 0; mf < 2; mf++) {
        int row0 = bm + warp_m * 32 + mf * 16 + (lane >> 2);
        int row1 = row0 + 8;
#pragma unroll
        for (int nf = 0; nf < 8; nf++) {
            int col = bn + warp_n * 64 + nf * 8 + (lane & 3) * 2;
            float2 bs = *(const float2*)(bias + col);
            float* a4 = acc[mf][nf];
            float2 o0 = make_float2(a4[0] + bs.x, a4[1] + bs.y);
            float2 o1 = make_float2(a4[2] + bs.x, a4[3] + bs.y);
            if (RESID) {
                float2 r0 = *(const float2*)(R + (size_t)row0 * ldr + col);
                float2 r1 = *(const float2*)(R + (size_t)row1 * ldr + col);
                o0.x += r0.x; o0.y += r0.y;
                o1.x += r1.x; o1.y += r1.y;
            }
            if (WF) {
                *(float2*)(Cf + (size_t)row0 * N + col) = o0;
                *(float2*)(Cf + (size_t)row1 * N + col) = o1;
            }
            if (WH) {
                *(__half2*)(Ch + (size_t)row0 * N + col) = __floats2half2_rn(o0.x, o0.y);
                *(__half2*)(Ch + (size_t)row1 * N + col) = __floats2half2_rn(o1.x, o1.y);
            }
        }
    }
#undef LDG_CHUNK
#undef STS_CHUNK
}

// ------------------------- banded attention (fp16 in/out) -------------------
// reads fused qkv buffer [M][3072] (q|k|v), writes g_ao [M][1024] fp16
__global__ __launch_bounds__(256) void band_attn(
    const __half* __restrict__ qkv, __half* __restrict__ o)
{
    int t = blockIdx.x, b = blockIdx.y;
    int hh = threadIdx.x >> 5;
    int lane = threadIdx.x & 31;
    const float scale = 0.088388347648318447f;  // 1/sqrt(128)

    size_t qb = ((size_t)(b*TT + t))*3072 + hh*DH + lane*4;
    float2 q01, q23;
    {
        const __half2* qp = (const __half2*)(qkv + qb);
        q01 = __half22float2(qp[0]);
        q23 = __half22float2(qp[1]);
    }

    float s[7];
    float m = -1e30f;
#pragma unroll
    for (int jj = 0; jj < 7; jj++) {
        int j = t - 3 + jj;
        bool ok = (j >= 0) && (j < TT);
        int jc = j < 0 ? 0 : (j > TT-1 ? TT-1 : j);
        size_t kb = ((size_t)(b*TT + jc))*3072 + 1024 + hh*DH + lane*4;
        const __half2* kp = (const __half2*)(qkv + kb);
        float2 k01 = __half22float2(kp[0]);
        float2 k23 = __half22float2(kp[1]);
        float d = q01.x*k01.x + q01.y*k01.y + q23.x*k23.x + q23.y*k23.y;
        d += __shfl_xor_sync(0xffffffffu, d, 16);
        d += __shfl_xor_sync(0xffffffffu, d, 8);
        d += __shfl_xor_sync(0xffffffffu, d, 4);
        d += __shfl_xor_sync(0xffffffffu, d, 2);
        d += __shfl_xor_sync(0xffffffffu, d, 1);
        d *= scale;
        s[jj] = ok ? d : -1e30f;
        m = fmaxf(m, s[jj]);
    }
    float sum = 0.f;
#pragma unroll
    for (int jj = 0; jj < 7; jj++) { s[jj] = expf(s[jj] - m); sum += s[jj]; }
    float inv = 1.f / sum;

    float4 acc = make_float4(0.f, 0.f, 0.f, 0.f);
#pragma unroll
    for (int jj = 0; jj < 7; jj++) {
        int j = t - 3 + jj;
        int jc = j < 0 ? 0 : (j > TT-1 ? TT-1 : j);
        size_t vb = ((size_t)(b*TT + jc))*3072 + 2048 + hh*DH + lane*4;
        const __half2* vp = (const __half2*)(qkv + vb);
        float2 v01 = __half22float2(vp[0]);
        float2 v23 = __half22float2(vp[1]);
        float p = s[jj] * inv;
        acc.x += p*v01.x; acc.y += p*v01.y; acc.z += p*v23.x; acc.w += p*v23.y;
    }
    size_t ob = ((size_t)(b*TT + t))*DD + hh*DH + lane*4;
    *(__half2*)(o + ob)     = __floats2half2_rn(acc.x, acc.y);
    *(__half2*)(o + ob + 2) = __floats2half2_rn(acc.z, acc.w);
}

// ------------------------- persistent bidirectional GRU ---------------------
// 128 CTAs: dir(2) x unit-group(8, 32 units) x batch-group(8, 4 batches)
__global__ __launch_bounds__(128) void gru_kernel(
    const float* __restrict__ gx,
    const float* __restrict__ Whf, const float* __restrict__ Whb,
    const float* __restrict__ bhf, const float* __restrict__ bhb,
    float* __restrict__ out)
{
    extern __shared__ float sm[];
    float* ws = sm;                   // [3*32][260]
    float* hs = sm + 3*32*260;        // [4][264]

    int cta = blockIdx.x;
    int dir = cta >> 6;
    int ug  = (cta >> 3) & 7;
    int bg  = cta & 7;
    int grp = (dir << 3) | bg;
    int tid = threadIdx.x;
    int u   = tid >> 2;
    int bl  = tid & 3;
    int unit  = ug*32 + u;
    int batch = bg*4 + bl;

    const float* Wh = dir ? Whb : Whf;
    const float* bh = dir ? bhb : bhf;

    for (int idx = tid; idx < 3*32*256; idx += 128) {
        int g   = idx >> 13;
        int rem = idx & 8191;
        int uu  = rem >> 8;
        int kk  = rem & 255;
        ws[(g*32 + uu)*260 + kk] = Wh[((g << 8) + ug*32 + uu)*256 + kk];
    }
    float br  = bh[unit];
    float bz  = bh[256 + unit];
    float bnn = bh[512 + unit];
    int len = g_len[batch];

    __stcg(&g_hstate[((dir*2 + 0)*BB + batch)*HID + unit], 0.f);
    __syncthreads();
    if (tid == 0) red_release(&g_bar[grp], 1u);

    const float* wr = &ws[(0*32 + u)*260];
    const float* wz = &ws[(1*32 + u)*260];
    const float* wn = &ws[(2*32 + u)*260];

    unsigned target = 8u;
    for (int s = 0; s < TT; s++, target += 8u) {
        // gx loads do not depend on h: issue before the barrier spin
        int tt;
        if (dir == 0) tt = s;
        else { int ti = len - 1 - s; tt = ti < 0 ? 0 : ti; }
        const float* gxp = gx + ((size_t)batch*TT + tt)*1536 + dir*768;
        float gr = gxp[unit];
        float gz = gxp[256 + unit];
        float gn = gxp[512 + unit];

        // all threads poll (acquire); no extra syncthreads needed
        while (ld_acq(&g_bar[grp]) < target) {}

        {
            const float* src = &g_hstate[((dir*2 + (s & 1))*BB + bg*4)*HID];
#pragma unroll
            for (int i = 0; i < 8; i++) {
                int idx = tid + i*128;
                int b2 = idx >> 8, k2 = idx & 255;
                hs[b2*264 + k2] = __ldcg(src + b2*256 + k2);
            }
        }
        __syncthreads();

        float4 ar = make_float4(0,0,0,0), az = ar, an = ar;
        const float* hb = &hs[bl*264];
#pragma unroll 8
        for (int kk = 0; kk < 256; kk += 4) {
            float4 h4 = *(const float4*)(hb + kk);
            float4 w1 = *(const float4*)(wr + kk);
            float4 w2 = *(const float4*)(wz + kk);
            float4 w3 = *(const float4*)(wn + kk);
            ar.x += h4.x*w1.x; ar.y += h4.y*w1.y; ar.z += h4.z*w1.z; ar.w += h4.w*w1.w;
            az.x += h4.x*w2.x; az.y += h4.y*w2.y; az.z += h4.z*w2.z; az.w += h4.w*w2.w;
            an.x += h4.x*w3.x; an.y += h4.y*w3.y; an.z += h4.z*w3.z; an.w += h4.w*w3.w;
        }
        float ghr = ar.x + ar.y + ar.z + ar.w;
        float ghz = az.x + az.y + az.z + az.w;
        float ghn = an.x + an.y + an.z + an.w;

        float r = 1.f / (1.f + expf(-(gr + ghr + br)));
        float z = 1.f / (1.f + expf(-(gz + ghz + bz)));
        float n = tanhf(gn + r*(ghn + bnn));
        float hp = hs[bl*264 + unit];
        float hn = (1.f - z)*n + z*hp;

        __stcg(&g_hstate[((dir*2 + ((s+1) & 1))*BB + batch)*HID + unit], hn);

        if (s < len) {
            int tout = (dir == 0) ? s : (len - 1 - s);
            float* op = out + ((size_t)batch*TT + tout)*512 + dir*256 + unit;
            *op += hn;
        }
        __syncthreads();
        if (tid == 0) red_release(&g_bar[grp], 1u);
    }
}

// ------------------------- launch ------------------------------------------
extern "C" void kernel_launch(void* const* d_in, const int* in_sizes, int n_in,
                              void* d_out, int out_size)
{
    const float* x      = (const float*)d_in[0];
    const int*   mask   = (const int*)  d_in[1];
    const float* W_tran = (const float*)d_in[2];
    const float* b_tran = (const float*)d_in[3];
    const float* Wq     = (const float*)d_in[4];
    const float* bq     = (const float*)d_in[5];
    const float* Wk     = (const float*)d_in[6];
    const float* bk     = (const float*)d_in[7];
    const float* Wv     = (const float*)d_in[8];
    const float* bv     = (const float*)d_in[9];
    const float* Wo     = (const float*)d_in[10];
    const float* bo     = (const float*)d_in[11];
    const float* Wihf   = (const float*)d_in[12];
    const float* Whhf   = (const float*)d_in[13];
    const float* bihf   = (const float*)d_in[14];
    const float* bhhf   = (const float*)d_in[15];
    const float* Wihb   = (const float*)d_in[16];
    const float* Whhb   = (const float*)d_in[17];
    const float* bihb   = (const float*)d_in[18];
    const float* bhhb   = (const float*)d_in[19];
    float* out = (float*)d_out;

    float *hbuf, *gxb, *biasbuf;
    __half *wh, *xh, *hh, *qkvh, *aoh;
    cudaGetSymbolAddress((void**)&hbuf,  g_h);
    cudaGetSymbolAddress((void**)&hh,    g_hh);
    cudaGetSymbolAddress((void**)&xh,    g_xh);
    cudaGetSymbolAddress((void**)&qkvh,  g_qkv);
    cudaGetSymbolAddress((void**)&aoh,   g_ao);
    cudaGetSymbolAddress((void**)&gxb,   g_gx);
    cudaGetSymbolAddress((void**)&wh,    g_Wh);
    cudaGetSymbolAddress((void**)&biasbuf, g_bias);

    const int smem_gru = (3*32*260 + 4*264) * 4;  // 104,064 B
    cudaFuncSetAttribute(gru_kernel, cudaFuncAttributeMaxDynamicSharedMemorySize, 112*1024);
    cudaFuncSetAttribute(gemm_h<false,true,false>,  cudaFuncAttributeMaxDynamicSharedMemorySize, GEMM_SMEM);
    cudaFuncSetAttribute(gemm_h<false,false,true>,  cudaFuncAttributeMaxDynamicSharedMemorySize, GEMM_SMEM);
    cudaFuncSetAttribute(gemm_h<true,true,true>,    cudaFuncAttributeMaxDynamicSharedMemorySize, GEMM_SMEM);

    prep_kernel<<<BB, 256>>>(mask);
    pack_bias<<<30, 256>>>(bq, bk, bv, bihf, bihb);
    xconv<<<(MTOT*XF/4 + 255)/256, 256>>>(x, xh, MTOT*XF/4);

    // weight convert/transpose to fp16 [N][K]
    {
        dim3 tb(32, 8);
        wtran_h<<<dim3(512/32, 1536/32), tb>>>(W_tran, wh + OFF_TRAN, 1536, 512);
        for (int l = 0; l < 2; l++) {
            size_t wo_ = (size_t)l * DD * DD;
            wtran_h<<<dim3(32, 32), tb>>>(Wq + wo_, wh + OFF_QKV(l) + 0*1048576, DD, DD);
            wtran_h<<<dim3(32, 32), tb>>>(Wk + wo_, wh + OFF_QKV(l) + 1*1048576, DD, DD);
            wtran_h<<<dim3(32, 32), tb>>>(Wv + wo_, wh + OFF_QKV(l) + 2*1048576, DD, DD);
            wtran_h<<<dim3(32, 32), tb>>>(Wo + wo_, wh + OFF_O(l), DD, DD);
        }
        wconv_h<<<(786432+255)/256, 256>>>(Wihf, wh + OFF_IH, 786432);
        wconv_h<<<(786432+255)/256, 256>>>(Wihb, wh + OFF_IH + 786432, 786432);
    }

    // x_face -> out (fp32)
    gemm_h<false,true,false><<<dim3(4, 64), 256, GEMM_SMEM>>>(
        xh + 1024, XF, wh + OFF_TRAN, b_tran, nullptr, 0, out, nullptr, 512, 1536);

    for (int l = 0; l < 2; l++) {
        const __half* Ain = (l == 0) ? xh : hh;
        int lda = (l == 0) ? XF : DD;

        // fused QKV: N = 3072, fp16 out
        gemm_h<false,false,true><<<dim3(24, 64), 256, GEMM_SMEM>>>(
            Ain, lda, wh + OFF_QKV(l), biasbuf + l*3072, nullptr, 0,
            nullptr, qkvh, 3072, DD);

        band_attn<<<dim3(TT, BB), 256>>>(qkvh, aoh);

        // O proj + residual: fp32 h and fp16 hh outputs
        const float* Rres = (l == 0) ? x : hbuf;
        int ldr = (l == 0) ? XF : DD;
        gemm_h<true,true,true><<<dim3(8, 64), 256, GEMM_SMEM>>>(
            aoh, DD, wh + OFF_O(l), bo + (size_t)l*DD, Rres, ldr,
            hbuf, hh, DD, DD);
    }

    // fused GRU input projections: N = 1536 (f | b), fp32 out
    gemm_h<false,true,false><<<dim3(12, 64), 256, GEMM_SMEM>>>(
        hh, DD, wh + OFF_IH, biasbuf + 6144, nullptr, 0, gxb, nullptr, 1536, DD);

    // persistent bidirectional GRU, writes out += ys
    gru_kernel<<<128, 128, smem_gru>>>(gxb, Whhf, Whhb, bhhf, bhhb, out);
}

// round 8
// speedup vs baseline: 3.4714x; 1.0184x over previous
#include <cuda_runtime.h>
#include <cuda_fp16.h>
#include <math.h>
#include <stdint.h>

// Problem constants
#define BB 32
#define TT 256
#define DD 1024
#define HH 8
#define DH 128
#define HID 256
#define MTOT (BB*TT)          // 8192
#define XF 2560

// ------------------------- scratch (static device memory) -------------------
__device__ float  g_h  [MTOT*DD];        // fp32 residual stream
__device__ __half g_hh [MTOT*DD];        // fp16 copy of h
__device__ __half g_xh [MTOT*XF];        // fp16 copy of x
__device__ __half g_qkv[MTOT*3072];      // fp16 qkv
__device__ __half g_ao [MTOT*DD];        // fp16 attention out
__device__ float  g_gx [MTOT*1536];      // fp32 GRU input projections
__device__ float  g_hstate[2*2*BB*HID];  // [dir][buf][batch][unit]
__device__ unsigned g_bar[16];
__device__ int g_len[BB];
__device__ float g_bias[2*3072 + 1536];

// fp16 weights, [N][K] layout
#define OFF_TRAN 0
#define OFF_QKV(l) (786432 + (size_t)(l)*3145728)
#define OFF_O(l)   (7077888 + (size_t)(l)*1048576)
#define OFF_IH     9175040
#define WH_ELEMS   10747904
__device__ __half g_Wh[WH_ELEMS];

// ------------------------- helpers ------------------------------------------
__device__ __forceinline__ uint32_t smem_u32(const void* p) {
    uint32_t a;
    asm("{ .reg .u64 t; cvta.to.shared.u64 t, %1; cvt.u32.u64 %0, t; }" : "=r"(a) : "l"(p));
    return a;
}
__device__ __forceinline__ void ldsm4(uint32_t* r, uint32_t addr) {
    asm volatile("ldmatrix.sync.aligned.m8n8.x4.shared.b16 {%0,%1,%2,%3}, [%4];"
        : "=r"(r[0]), "=r"(r[1]), "=r"(r[2]), "=r"(r[3]) : "r"(addr));
}
__device__ __forceinline__ void mma_fp16(float* c, const uint32_t* a, uint32_t b0, uint32_t b1) {
    asm volatile(
        "mma.sync.aligned.m16n8k16.row.col.f32.f16.f16.f32 "
        "{%0,%1,%2,%3}, {%4,%5,%6,%7}, {%8,%9}, {%0,%1,%2,%3};"
        : "+f"(c[0]), "+f"(c[1]), "+f"(c[2]), "+f"(c[3])
        : "r"(a[0]), "r"(a[1]), "r"(a[2]), "r"(a[3]), "r"(b0), "r"(b1));
}
__device__ __forceinline__ void cp16(uint32_t sdst, const void* gsrc) {
    asm volatile("cp.async.cg.shared.global [%0], [%1], 16;" :: "r"(sdst), "l"(gsrc));
}
#define CP_COMMIT() asm volatile("cp.async.commit_group;" ::: "memory")
#define CP_WAIT3()  asm volatile("cp.async.wait_group 3;" ::: "memory")
__device__ __forceinline__ unsigned ld_acq(const unsigned* p) {
    unsigned v;
    asm volatile("ld.acquire.gpu.global.u32 %0, [%1];" : "=r"(v) : "l"(p) : "memory");
    return v;
}
__device__ __forceinline__ void red_release(unsigned* p, unsigned v) {
    asm volatile("red.release.gpu.global.add.u32 [%0], %1;" :: "l"(p), "r"(v) : "memory");
}

// ------------------------- fused prep kernel --------------------------------
// one launch: lengths+bar reset | bias pack | W_tran transpose | QKVO transposes
// | W_ih converts | x -> fp16
#define PB0 32                       // prep:      [0, 32)
#define PB1 (PB0 + 30)               // pack_bias: [32, 62)
#define PB2 (PB1 + 768)              // tran:      [62, 830)      16 x 48 tiles
#define PB3 (PB2 + 8192)             // qkvo:      [830, 9022)    8 x (32x32)
#define PB4 (PB3 + 768)              // ih conv:   [9022, 9790)   2 x 384
#define PB5 (PB4 + 10240)            // xconv:     [9790, 20030)
__global__ __launch_bounds__(256) void wprep(
    const int* __restrict__ mask,
    const float* __restrict__ bq, const float* __restrict__ bk, const float* __restrict__ bv,
    const float* __restrict__ bihf, const float* __restrict__ bihb,
    const float* __restrict__ W_tran,
    const float* __restrict__ Wq, const float* __restrict__ Wk,
    const float* __restrict__ Wv, const float* __restrict__ Wo,
    const float* __restrict__ Wihf, const float* __restrict__ Wihb,
    const float* __restrict__ x,
    __half* __restrict__ wh, __half* __restrict__ xh)
{
    __shared__ __align__(16) char shbuf[32*33*4];
    int b = blockIdx.x;
    int tid = threadIdx.x;

    if (b < PB0) {
        int* red = (int*)shbuf;
        red[tid] = mask[b*TT + tid];
        __syncthreads();
        for (int st = 128; st > 0; st >>= 1) {
            if (tid < st) red[tid] += red[tid + st];
            __syncthreads();
        }
        if (tid == 0) g_len[b] = red[0];
        if (b == 0 && tid < 16) g_bar[tid] = 0u;
    } else if (b < PB1) {
        int idx = (b - PB0) * 256 + tid;
        if (idx < 6144) {
            int l = idx / 3072, j = idx % 3072;
            float v;
            if (j < 1024)      v = bq[l*1024 + j];
            else if (j < 2048) v = bk[l*1024 + j - 1024];
            else               v = bv[l*1024 + j - 2048];
            g_bias[idx] = v;
        } else {
            int j = idx - 6144;
            g_bias[idx] = (j < 768) ? bihf[j] : bihb[j - 768];
        }
    } else if (b < PB3) {
        // transpose 32x32 tile: W [K][N] -> wh [N][K]
        const float* W; __half* out; int K, N, bx, by;
        if (b < PB2) {
            int i2 = b - PB1;
            W = W_tran; out = wh + OFF_TRAN; K = 1536; N = 512;
            bx = i2 & 15; by = i2 >> 4;
        } else {
            int i2 = b - PB2;
            int unit = i2 >> 10, w = i2 & 1023;
            int l = unit >> 2, j = unit & 3;
            const float* src = (j == 0) ? Wq : (j == 1) ? Wk : (j == 2) ? Wv : Wo;
            W = src + (size_t)l * DD * DD;
            out = (j < 3) ? (wh + OFF_QKV(l) + (size_t)j * 1048576) : (wh + OFF_O(l));
            K = DD; N = DD;
            bx = w & 31; by = w >> 5;
        }
        float (*ts)[33] = (float(*)[33])shbuf;
        int tx = tid & 31, ty = tid >> 5;
        int n0 = bx * 32, k0 = by * 32;
#pragma unroll
        for (int i = 0; i < 4; i++)
            ts[ty + i*8][tx] = W[(size_t)(k0 + ty + i*8) * N + n0 + tx];
        __syncthreads();
#pragma unroll
        for (int i = 0; i < 4; i++) {
            int n = n0 + ty + i*8, k = k0 + tx;
            out[(size_t)n * K + k] = __float2half_rn(ts[tx][ty + i*8]);
        }
    } else if (b < PB4) {
        int i2 = b - PB3;
        const float* src = (i2 < 384) ? Wihf : Wihb;
        __half* dst = wh + OFF_IH + ((i2 < 384) ? 0 : 786432);
        int base = ((i2 < 384) ? i2 : i2 - 384) * 256 + tid;  // 8-elem unit
        float4 f0 = ((const float4*)src)[base*2];
        float4 f1 = ((const float4*)src)[base*2 + 1];
        __half2 h0 = __floats2half2_rn(f0.x, f0.y);
        __half2 h1 = __floats2half2_rn(f0.z, f0.w);
        __half2 h2 = __floats2half2_rn(f1.x, f1.y);
        __half2 h3 = __floats2half2_rn(f1.z, f1.w);
        uint4 u;
        u.x = *reinterpret_cast<uint32_t*>(&h0);
        u.y = *reinterpret_cast<uint32_t*>(&h1);
        u.z = *reinterpret_cast<uint32_t*>(&h2);
        u.w = *reinterpret_cast<uint32_t*>(&h3);
        ((uint4*)dst)[base] = u;
    } else {
        int base = (b - PB4) * 256 + tid;   // 8-elem unit, total 2,621,440 units
        float4 f0 = ((const float4*)x)[base*2];
        float4 f1 = ((const float4*)x)[base*2 + 1];
        __half2 h0 = __floats2half2_rn(f0.x, f0.y);
        __half2 h1 = __floats2half2_rn(f0.z, f0.w);
        __half2 h2 = __floats2half2_rn(f1.x, f1.y);
        __half2 h3 = __floats2half2_rn(f1.z, f1.w);
        uint4 u;
        u.x = *reinterpret_cast<uint32_t*>(&h0);
        u.y = *reinterpret_cast<uint32_t*>(&h1);
        u.z = *reinterpret_cast<uint32_t*>(&h2);
        u.w = *reinterpret_cast<uint32_t*>(&h3);
        ((uint4*)xh)[base] = u;
    }
}

// ------------------------- HMMA fp16 GEMM, cp.async 5-stage -----------------
// C = A[M,K](fp16) * B[N,K](fp16)^T + bias (+R fp32)
// outputs: Cf (fp32) if WF, Ch (fp16) if WH
// grid (N/128, M/128), 256 threads (8 warps: 4m x 2n), K % 32 == 0, K/32 >= 4.
#define TILEB 10240                   // 128 rows * 80B
#define STAGE_B (2*TILEB)             // 20480
#define NSTAGE 5
#define GEMM_SMEM (NSTAGE*STAGE_B)    // 102400

template<bool RESID, bool WF, bool WH>
__global__ __launch_bounds__(256) void gemm_h(
    const __half* __restrict__ A, int lda,
    const __half* __restrict__ B,
    const float* __restrict__ bias,
    const float* __restrict__ R, int ldr,
    float* __restrict__ Cf, __half* __restrict__ Ch,
    int N, int K)
{
    extern __shared__ char smem[];
    uint32_t sb = smem_u32(smem);
    int tid = threadIdx.x;
    int lane = tid & 31;
    int wid = tid >> 5;
    int warp_m = wid & 3;      // 0..3
    int warp_n = wid >> 2;     // 0..1
    int bn = blockIdx.x * 128, bm = blockIdx.y * 128;

    float acc[2][8][4];
#pragma unroll
    for (int a = 0; a < 2; a++)
#pragma unroll
        for (int b = 0; b < 8; b++)
#pragma unroll
            for (int c = 0; c < 4; c++) acc[a][b][c] = 0.f;

#define ISSUE(k0idx, stg)                                                      \
    {                                                                          \
        int k0 = (k0idx) * 32;                                                 \
        uint32_t sa = sb + (stg) * STAGE_B;                                    \
        _Pragma("unroll")                                                      \
        for (int i = 0; i < 2; i++) {                                          \
            int linear = tid + i * 256;                                        \
            int row = linear >> 2, cc = linear & 3;                            \
            cp16(sa + row*80 + cc*16,                                          \
                 A + (size_t)(bm + row) * lda + k0 + cc*8);                    \
            cp16(sa + TILEB + row*80 + cc*16,                                  \
                 B + (size_t)(bn + row) * K + k0 + cc*8);                      \
        }                                                                      \
    }

    const int NC = K / 32;
    // prologue: 4 chunks in flight
#pragma unroll
    for (int p = 0; p < 4; p++) {
        ISSUE(p, p);
        CP_COMMIT();
    }

    for (int ch = 0; ch < NC; ch++) {
        CP_WAIT3();
        __syncthreads();

        uint32_t sbase = sb + (ch % NSTAGE) * STAGE_B;
#pragma unroll
        for (int ks = 0; ks < 2; ks++) {
            int kofs = ks * 32;   // bytes (16 halfs)
            uint32_t ah[2][4];
#pragma unroll
            for (int mf = 0; mf < 2; mf++) {
                uint32_t row = warp_m * 32 + mf * 16 + (lane & 15);
                uint32_t addr = sbase + row * 80 + kofs + ((lane >> 4) * 16);
                ldsm4(ah[mf], addr);
            }
#pragma unroll
            for (int np = 0; np < 4; np++) {
                uint32_t rown = warp_n * 64 + np * 16 + (lane & 7) + ((lane >> 4) << 3);
                uint32_t addr = sbase + TILEB + rown * 80 + kofs + (((lane >> 3) & 1) * 16);
                uint32_t b[4];
                ldsm4(b, addr);
#pragma unroll
                for (int mf = 0; mf < 2; mf++) {
                    mma_fp16(acc[mf][np*2],   ah[mf], b[0], b[1]);
                    mma_fp16(acc[mf][np*2+1], ah[mf], b[2], b[3]);
                }
            }
        }

        int nxt = ch + 4;
        if (nxt < NC) ISSUE(nxt, nxt % NSTAGE);
        CP_COMMIT();
    }

    // ---- epilogue ----
#pragma unroll
    for (int mf = 0; mf < 2; mf++) {
        int row0 = bm + warp_m * 32 + mf * 16 + (lane >> 2);
        int row1 = row0 + 8;
#pragma unroll
        for (int nf = 0; nf < 8; nf++) {
            int col = bn + warp_n * 64 + nf * 8 + (lane & 3) * 2;
            float2 bs = *(const float2*)(bias + col);
            float* a4 = acc[mf][nf];
            float2 o0 = make_float2(a4[0] + bs.x, a4[1] + bs.y);
            float2 o1 = make_float2(a4[2] + bs.x, a4[3] + bs.y);
            if (RESID) {
                float2 r0 = *(const float2*)(R + (size_t)row0 * ldr + col);
                float2 r1 = *(const float2*)(R + (size_t)row1 * ldr + col);
                o0.x += r0.x; o0.y += r0.y;
                o1.x += r1.x; o1.y += r1.y;
            }
            if (WF) {
                *(float2*)(Cf + (size_t)row0 * N + col) = o0;
                *(float2*)(Cf + (size_t)row1 * N + col) = o1;
            }
            if (WH) {
                *(__half2*)(Ch + (size_t)row0 * N + col) = __floats2half2_rn(o0.x, o0.y);
                *(__half2*)(Ch + (size_t)row1 * N + col) = __floats2half2_rn(o1.x, o1.y);
            }
        }
    }
#undef ISSUE
}

// ------------------------- banded attention (fp16 in/out) -------------------
__global__ __launch_bounds__(256) void band_attn(
    const __half* __restrict__ qkv, __half* __restrict__ o)
{
    int t = blockIdx.x, b = blockIdx.y;
    int hh = threadIdx.x >> 5;
    int lane = threadIdx.x & 31;
    const float scale = 0.088388347648318447f;  // 1/sqrt(128)

    size_t qb = ((size_t)(b*TT + t))*3072 + hh*DH + lane*4;
    float2 q01, q23;
    {
        const __half2* qp = (const __half2*)(qkv + qb);
        q01 = __half22float2(qp[0]);
        q23 = __half22float2(qp[1]);
    }

    float s[7];
    float m = -1e30f;
#pragma unroll
    for (int jj = 0; jj < 7; jj++) {
        int j = t - 3 + jj;
        bool ok = (j >= 0) && (j < TT);
        int jc = j < 0 ? 0 : (j > TT-1 ? TT-1 : j);
        size_t kb = ((size_t)(b*TT + jc))*3072 + 1024 + hh*DH + lane*4;
        const __half2* kp = (const __half2*)(qkv + kb);
        float2 k01 = __half22float2(kp[0]);
        float2 k23 = __half22float2(kp[1]);
        float d = q01.x*k01.x + q01.y*k01.y + q23.x*k23.x + q23.y*k23.y;
        d += __shfl_xor_sync(0xffffffffu, d, 16);
        d += __shfl_xor_sync(0xffffffffu, d, 8);
        d += __shfl_xor_sync(0xffffffffu, d, 4);
        d += __shfl_xor_sync(0xffffffffu, d, 2);
        d += __shfl_xor_sync(0xffffffffu, d, 1);
        d *= scale;
        s[jj] = ok ? d : -1e30f;
        m = fmaxf(m, s[jj]);
    }
    float sum = 0.f;
#pragma unroll
    for (int jj = 0; jj < 7; jj++) { s[jj] = expf(s[jj] - m); sum += s[jj]; }
    float inv = 1.f / sum;

    float4 acc = make_float4(0.f, 0.f, 0.f, 0.f);
#pragma unroll
    for (int jj = 0; jj < 7; jj++) {
        int j = t - 3 + jj;
        int jc = j < 0 ? 0 : (j > TT-1 ? TT-1 : j);
        size_t vb = ((size_t)(b*TT + jc))*3072 + 2048 + hh*DH + lane*4;
        const __half2* vp = (const __half2*)(qkv + vb);
        float2 v01 = __half22float2(vp[0]);
        float2 v23 = __half22float2(vp[1]);
        float p = s[jj] * inv;
        acc.x += p*v01.x; acc.y += p*v01.y; acc.z += p*v23.x; acc.w += p*v23.y;
    }
    size_t ob = ((size_t)(b*TT + t))*DD + hh*DH + lane*4;
    *(__half2*)(o + ob)     = __floats2half2_rn(acc.x, acc.y);
    *(__half2*)(o + ob + 2) = __floats2half2_rn(acc.z, acc.w);
}

// ------------------------- persistent bidirectional GRU ---------------------
__global__ __launch_bounds__(128) void gru_kernel(
    const float* __restrict__ gx,
    const float* __restrict__ Whf, const float* __restrict__ Whb,
    const float* __restrict__ bhf, const float* __restrict__ bhb,
    float* __restrict__ out)
{
    extern __shared__ float sm[];
    float* ws = sm;                   // [3*32][260]
    float* hs = sm + 3*32*260;        // [4][264]

    int cta = blockIdx.x;
    int dir = cta >> 6;
    int ug  = (cta >> 3) & 7;
    int bg  = cta & 7;
    int grp = (dir << 3) | bg;
    int tid = threadIdx.x;
    int u   = tid >> 2;
    int bl  = tid & 3;
    int unit  = ug*32 + u;
    int batch = bg*4 + bl;

    const float* Wh = dir ? Whb : Whf;
    const float* bh = dir ? bhb : bhf;

    for (int idx = tid; idx < 3*32*256; idx += 128) {
        int g   = idx >> 13;
        int rem = idx & 8191;
        int uu  = rem >> 8;
        int kk  = rem & 255;
        ws[(g*32 + uu)*260 + kk] = Wh[((g << 8) + ug*32 + uu)*256 + kk];
    }
    float br  = bh[unit];
    float bz  = bh[256 + unit];
    float bnn = bh[512 + unit];
    int len = g_len[batch];

    __stcg(&g_hstate[((dir*2 + 0)*BB + batch)*HID + unit], 0.f);
    __syncthreads();
    if (tid == 0) red_release(&g_bar[grp], 1u);

    const float* wr = &ws[(0*32 + u)*260];
    const float* wz = &ws[(1*32 + u)*260];
    const float* wn = &ws[(2*32 + u)*260];

    unsigned target = 8u;
    for (int s = 0; s < TT; s++, target += 8u) {
        int tt;
        if (dir == 0) tt = s;
        else { int ti = len - 1 - s; tt = ti < 0 ? 0 : ti; }
        const float* gxp = gx + ((size_t)batch*TT + tt)*1536 + dir*768;
        float gr = gxp[unit];
        float gz = gxp[256 + unit];
        float gn = gxp[512 + unit];

        while (ld_acq(&g_bar[grp]) < target) {}

        {
            const float* src = &g_hstate[((dir*2 + (s & 1))*BB + bg*4)*HID];
#pragma unroll
            for (int i = 0; i < 8; i++) {
                int idx = tid + i*128;
                int b2 = idx >> 8, k2 = idx & 255;
                hs[b2*264 + k2] = __ldcg(src + b2*256 + k2);
            }
        }
        __syncthreads();

        float4 ar = make_float4(0,0,0,0), az = ar, an = ar;
        const float* hb = &hs[bl*264];
#pragma unroll 8
        for (int kk = 0; kk < 256; kk += 4) {
            float4 h4 = *(const float4*)(hb + kk);
            float4 w1 = *(const float4*)(wr + kk);
            float4 w2 = *(const float4*)(wz + kk);
            float4 w3 = *(const float4*)(wn + kk);
            ar.x += h4.x*w1.x; ar.y += h4.y*w1.y; ar.z += h4.z*w1.z; ar.w += h4.w*w1.w;
            az.x += h4.x*w2.x; az.y += h4.y*w2.y; az.z += h4.z*w2.z; az.w += h4.w*w2.w;
            an.x += h4.x*w3.x; an.y += h4.y*w3.y; an.z += h4.z*w3.z; an.w += h4.w*w3.w;
        }
        float ghr = ar.x + ar.y + ar.z + ar.w;
        float ghz = az.x + az.y + az.z + az.w;
        float ghn = an.x + an.y + an.z + an.w;

        float r = 1.f / (1.f + expf(-(gr + ghr + br)));
        float z = 1.f / (1.f + expf(-(gz + ghz + bz)));
        float n = tanhf(gn + r*(ghn + bnn));
        float hp = hs[bl*264 + unit];
        float hn = (1.f - z)*n + z*hp;

        __stcg(&g_hstate[((dir*2 + ((s+1) & 1))*BB + batch)*HID + unit], hn);

        if (s < len) {
            int tout = (dir == 0) ? s : (len - 1 - s);
            float* op = out + ((size_t)batch*TT + tout)*512 + dir*256 + unit;
            *op += hn;
        }
        __syncthreads();
        if (tid == 0) red_release(&g_bar[grp], 1u);
    }
}

// ------------------------- launch ------------------------------------------
extern "C" void kernel_launch(void* const* d_in, const int* in_sizes, int n_in,
                              void* d_out, int out_size)
{
    const float* x      = (const float*)d_in[0];
    const int*   mask   = (const int*)  d_in[1];
    const float* W_tran = (const float*)d_in[2];
    const float* b_tran = (const float*)d_in[3];
    const float* Wq     = (const float*)d_in[4];
    const float* bq     = (const float*)d_in[5];
    const float* Wk     = (const float*)d_in[6];
    const float* bk     = (const float*)d_in[7];
    const float* Wv     = (const float*)d_in[8];
    const float* bv     = (const float*)d_in[9];
    const float* Wo     = (const float*)d_in[10];
    const float* bo     = (const float*)d_in[11];
    const float* Wihf   = (const float*)d_in[12];
    const float* Whhf   = (const float*)d_in[13];
    const float* bihf   = (const float*)d_in[14];
    const float* bhhf   = (const float*)d_in[15];
    const float* Wihb   = (const float*)d_in[16];
    const float* Whhb   = (const float*)d_in[17];
    const float* bihb   = (const float*)d_in[18];
    const float* bhhb   = (const float*)d_in[19];
    float* out = (float*)d_out;

    float *hbuf, *gxb, *biasbuf;
    __half *wh, *xh, *hh, *qkvh, *aoh;
    cudaGetSymbolAddress((void**)&hbuf,  g_h);
    cudaGetSymbolAddress((void**)&hh,    g_hh);
    cudaGetSymbolAddress((void**)&xh,    g_xh);
    cudaGetSymbolAddress((void**)&qkvh,  g_qkv);
    cudaGetSymbolAddress((void**)&aoh,   g_ao);
    cudaGetSymbolAddress((void**)&gxb,   g_gx);
    cudaGetSymbolAddress((void**)&wh,    g_Wh);
    cudaGetSymbolAddress((void**)&biasbuf, g_bias);

    const int smem_gru = (3*32*260 + 4*264) * 4;  // 104,064 B
    cudaFuncSetAttribute(gru_kernel, cudaFuncAttributeMaxDynamicSharedMemorySize, 112*1024);
    cudaFuncSetAttribute(gemm_h<false,true,false>,  cudaFuncAttributeMaxDynamicSharedMemorySize, GEMM_SMEM);
    cudaFuncSetAttribute(gemm_h<false,false,true>,  cudaFuncAttributeMaxDynamicSharedMemorySize, GEMM_SMEM);
    cudaFuncSetAttribute(gemm_h<true,true,true>,    cudaFuncAttributeMaxDynamicSharedMemorySize, GEMM_SMEM);

    // one fused prep launch
    wprep<<<PB5, 256>>>(mask, bq, bk, bv, bihf, bihb,
                        W_tran, Wq, Wk, Wv, Wo, Wihf, Wihb, x, wh, xh);

    // x_face -> out (fp32)
    gemm_h<false,true,false><<<dim3(4, 64), 256, GEMM_SMEM>>>(
        xh + 1024, XF, wh + OFF_TRAN, b_tran, nullptr, 0, out, nullptr, 512, 1536);

    for (int l = 0; l < 2; l++) {
        const __half* Ain = (l == 0) ? xh : hh;
        int lda = (l == 0) ? XF : DD;

        // fused QKV: N = 3072, fp16 out
        gemm_h<false,false,true><<<dim3(24, 64), 256, GEMM_SMEM>>>(
            Ain, lda, wh + OFF_QKV(l), biasbuf + l*3072, nullptr, 0,
            nullptr, qkvh, 3072, DD);

        band_attn<<<dim3(TT, BB), 256>>>(qkvh, aoh);

        // O proj + residual: fp32 h and fp16 hh outputs
        const float* Rres = (l == 0) ? x : hbuf;
        int ldr = (l == 0) ? XF : DD;
        gemm_h<true,true,true><<<dim3(8, 64), 256, GEMM_SMEM>>>(
            aoh, DD, wh + OFF_O(l), bo + (size_t)l*DD, Rres, ldr,
            hbuf, hh, DD, DD);
    }

    // fused GRU input projections: N = 1536 (f | b), fp32 out
    gemm_h<false,true,false><<<dim3(12, 64), 256, GEMM_SMEM>>>(
        hh, DD, wh + OFF_IH, biasbuf + 6144, nullptr, 0, gxb, nullptr, 1536, DD);

    // persistent bidirectional GRU, writes out += ys
    gru_kernel<<<128, 128, smem_gru>>>(gxb, Whhf, Whhb, bhhf, bhhb, out);
}